// round 6
// baseline (speedup 1.0000x reference)
#include <cuda_runtime.h>
#include <cstdint>

// ---------------------------------------------------------------------------
// Problem constants
// ---------------------------------------------------------------------------
#define HH   56
#define WWID 56
#define DDEP 28
#define LTOK 87808          // 56*56*28
#define CDIM 96
#define NWIN 256
#define NTOK 343
#define NHEAD 3
#define FF   384
#define BN   96             // GEMM N tile
#define BM   128            // GEMM M tile
#define KPAD 36             // smem row stride (floats)

// ---------------------------------------------------------------------------
// Scratch (device globals; no allocation allowed)
// ---------------------------------------------------------------------------
__device__ __align__(16) float g_H  [(size_t)LTOK * CDIM];
__device__ __align__(16) float g_QKV[(size_t)LTOK * 288];
__device__ __align__(16) float g_O  [(size_t)LTOK * CDIM];
__device__ __align__(16) float g_X  [(size_t)LTOK * CDIM];
__device__ __align__(16) float g_X2 [(size_t)LTOK * CDIM];
__device__ __align__(16) float g_FF [(size_t)LTOK * FF];
__device__ int g_DST[LTOK];
// pre-transposed weights [N,K]
__device__ __align__(16) float g_WtQKV [288 * 96];
__device__ __align__(16) float g_WtPROJ[96 * 96];
__device__ __align__(16) float g_WtFC1 [384 * 96];
__device__ __align__(16) float g_WtFC2 [96 * 384];

// ---------------------------------------------------------------------------
// helpers
// ---------------------------------------------------------------------------
__device__ __forceinline__ void mma8(float* c, const uint32_t* a, uint32_t b0, uint32_t b1) {
    asm("mma.sync.aligned.m16n8k8.row.col.f32.tf32.tf32.f32 "
        "{%0,%1,%2,%3}, {%4,%5,%6,%7}, {%8,%9}, {%0,%1,%2,%3};"
        : "+f"(c[0]), "+f"(c[1]), "+f"(c[2]), "+f"(c[3])
        : "r"(a[0]), "r"(a[1]), "r"(a[2]), "r"(a[3]), "r"(b0), "r"(b1));
}

// ---------------------------------------------------------------------------
// LayerNorm #1 (one warp per token): gather + shift + window partition
// ---------------------------------------------------------------------------
__global__ void __launch_bounds__(256) ln_kernel(const float* __restrict__ in,
                                                 const float* __restrict__ gamma,
                                                 const float* __restrict__ beta)
{
    int gw   = (blockIdx.x * 256 + threadIdx.x) >> 5;
    int lane = threadIdx.x & 31;
    if (gw >= LTOK) return;

    int w = gw / NTOK, n = gw - w * NTOK;
    int iH = w >> 5, iW = (w >> 2) & 7, iD = w & 3;
    int a = n / 49; int r = n - a * 49; int b = r / 7; int c = r - b * 7;
    int th = iH * 7 + a + 3; if (th >= HH)   th -= HH;
    int tw = iW * 7 + b + 3; if (tw >= WWID) tw -= WWID;
    int td = iD * 7 + c + 3; if (td >= DDEP) td -= DDEP;
    int src = (th * WWID + tw) * DDEP + td;
    if (lane == 0) g_DST[gw] = src;
    const float* inp  = in + (size_t)src * CDIM;
    float* outp = g_H + (size_t)gw * CDIM;

    float v0 = inp[lane], v1 = inp[lane + 32], v2 = inp[lane + 64];
    float s  = v0 + v1 + v2;
    float ss = fmaf(v0, v0, fmaf(v1, v1, v2 * v2));
#pragma unroll
    for (int o = 16; o; o >>= 1) {
        s  += __shfl_xor_sync(0xffffffffu, s, o);
        ss += __shfl_xor_sync(0xffffffffu, ss, o);
    }
    float mean = s * (1.0f / 96.0f);
    float var  = ss * (1.0f / 96.0f) - mean * mean;
    float inv  = rsqrtf(var + 1e-5f);
    outp[lane]      = (v0 - mean) * inv * gamma[lane]      + beta[lane];
    outp[lane + 32] = (v1 - mean) * inv * gamma[lane + 32] + beta[lane + 32];
    outp[lane + 64] = (v2 - mean) * inv * gamma[lane + 64] + beta[lane + 64];
}

// ---------------------------------------------------------------------------
// All weight transposes in one launch: W[K,N] -> Wt[N,K]
// ---------------------------------------------------------------------------
__global__ void transpose_all(const float* __restrict__ qkv_w,
                              const float* __restrict__ proj_w,
                              const float* __restrict__ fc1_w,
                              const float* __restrict__ fc2_w)
{
    int idx = blockIdx.x * 256 + threadIdx.x;
    if (idx < 27648) {                       // qkv 96x288
        int k = idx / 288, n = idx - k * 288;
        g_WtQKV[n * 96 + k] = qkv_w[idx];
    } else if (idx < 36864) {                // proj 96x96
        int j = idx - 27648;
        int k = j / 96, n = j - k * 96;
        g_WtPROJ[n * 96 + k] = proj_w[j];
    } else if (idx < 73728) {                // fc1 96x384
        int j = idx - 36864;
        int k = j / 384, n = j - k * 384;
        g_WtFC1[n * 96 + k] = fc1_w[j];
    } else if (idx < 110592) {               // fc2 384x96
        int j = idx - 73728;
        int k = j / 96, n = j - k * 96;
        g_WtFC2[n * 384 + k] = fc2_w[j];
    }
}

// ---------------------------------------------------------------------------
// Double-buffered mma.sync tf32 GEMM: C[128,96] = A[128,K] @ Wt[96,K]^T
// Raw fp32 bits fed to tf32 mma (HW truncation, CUTLASS fast path).
// MODE 0: qkv (q-scale)  MODE 1: proj (scatter+residual + fused LN2)
// MODE 2: fc1 (GELU)     MODE 3: fc2 (+residual -> d_out)
// ---------------------------------------------------------------------------
#define ABUF 4608            // 128*36 words
#define BBUF 3456            // 96*36 words
#define GEMM_SMEM ((2 * ABUF + 2 * BBUF) * 4)   // 64512 B; epilogue aliases

template <int MODE>
__global__ void __launch_bounds__(256) gemm_mma(const float* __restrict__ bias,
                                                const float* __restrict__ res,
                                                float* __restrict__ outp,
                                                int K,
                                                const float* __restrict__ g2,
                                                const float* __restrict__ b2)
{
    extern __shared__ __align__(16) char smraw[];
    uint32_t* Au = (uint32_t*)smraw;                  // [2][128][36]
    uint32_t* Bu = (uint32_t*)(smraw + 2 * ABUF * 4); // [2][96][36]
    float*    Sf = (float*)smraw;                     // epilogue [128][97]

    const float* A  = (MODE == 0) ? g_H : (MODE == 1) ? g_O : (MODE == 2) ? g_X2 : g_FF;
    const float* Wt = (MODE == 0) ? g_WtQKV : (MODE == 1) ? g_WtPROJ
                    : (MODE == 2) ? g_WtFC1 : g_WtFC2;

    int tid  = threadIdx.x;
    int wid  = tid >> 5, lane = tid & 31;
    int wr   = wid >> 1, wc = wid & 1;
    int g    = lane >> 2, c = lane & 3;
    int m0   = blockIdx.y * BM;
    int n0   = blockIdx.x * BN;

    int arow = tid >> 3, aq = (tid & 7) << 2;
    const float* Aptr = A + (size_t)(m0 + arow) * K + aq;
    int brow = tid >> 3;
    const float* Bptr = Wt + (size_t)(n0 + brow) * K + aq;

    float4 ra[4], rb[3];
#pragma unroll
    for (int i = 0; i < 4; i++)
        ra[i] = *(const float4*)(Aptr + (size_t)(i << 5) * K);
#pragma unroll
    for (int i = 0; i < 3; i++)
        rb[i] = *(const float4*)(Bptr + (size_t)(i << 5) * K);

    auto stage = [&](int b) {
        uint32_t* Ad = Au + b * ABUF;
        uint32_t* Bd = Bu + b * BBUF;
#pragma unroll
        for (int i = 0; i < 4; i++)
            *(float4*)(Ad + (arow + (i << 5)) * KPAD + aq) = ra[i];
#pragma unroll
        for (int i = 0; i < 3; i++)
            *(float4*)(Bd + (brow + (i << 5)) * KPAD + aq) = rb[i];
    };

    stage(0);
    __syncthreads();

    float acc[2][6][4];
#pragma unroll
    for (int t = 0; t < 2; t++)
#pragma unroll
        for (int u = 0; u < 6; u++)
#pragma unroll
            for (int j = 0; j < 4; j++) acc[t][u][j] = 0.0f;

    int nc = K >> 5;
    for (int ch = 0; ch < nc; ch++) {
        if (ch + 1 < nc) {
            int k1 = (ch + 1) << 5;
#pragma unroll
            for (int i = 0; i < 4; i++)
                ra[i] = *(const float4*)(Aptr + (size_t)(i << 5) * K + k1);
#pragma unroll
            for (int i = 0; i < 3; i++)
                rb[i] = *(const float4*)(Bptr + (size_t)(i << 5) * K + k1);
        }
        const uint32_t* As = Au + (ch & 1) * ABUF;
        const uint32_t* Bs = Bu + (ch & 1) * BBUF;
#pragma unroll
        for (int ks = 0; ks < 4; ks++) {
            int kk = (ks << 3) + c;
            uint32_t a[2][4];
#pragma unroll
            for (int t = 0; t < 2; t++) {
                int r0 = wr * 32 + t * 16 + g;
                a[t][0] = As[r0 * KPAD + kk];
                a[t][1] = As[(r0 + 8) * KPAD + kk];
                a[t][2] = As[r0 * KPAD + kk + 4];
                a[t][3] = As[(r0 + 8) * KPAD + kk + 4];
            }
#pragma unroll
            for (int u = 0; u < 6; u++) {
                int nb = wc * 48 + u * 8 + g;
                uint32_t b0 = Bs[nb * KPAD + kk];
                uint32_t b1 = Bs[nb * KPAD + kk + 4];
                mma8(acc[0][u], a[0], b0, b1);
                mma8(acc[1][u], a[1], b0, b1);
            }
        }
        if (ch + 1 < nc) {
            stage((ch + 1) & 1);
            __syncthreads();
        }
    }
    __syncthreads();

#pragma unroll
    for (int t = 0; t < 2; t++) {
#pragma unroll
        for (int u = 0; u < 6; u++) {
            int r0 = wr * 32 + t * 16 + g;
            int nn = wc * 48 + u * 8 + 2 * c;
            float b0 = __ldg(bias + n0 + nn);
            float b1 = __ldg(bias + n0 + nn + 1);
            float v0 = acc[t][u][0] + b0, v1 = acc[t][u][1] + b1;
            float v2 = acc[t][u][2] + b0, v3 = acc[t][u][3] + b1;
            if (MODE == 0 && n0 == 0) {
                v0 *= 0.17677669529663689f; v1 *= 0.17677669529663689f;
                v2 *= 0.17677669529663689f; v3 *= 0.17677669529663689f;
            }
            if (MODE == 2) {
                v0 = 0.5f * v0 * (1.0f + erff(v0 * 0.70710678118654752f));
                v1 = 0.5f * v1 * (1.0f + erff(v1 * 0.70710678118654752f));
                v2 = 0.5f * v2 * (1.0f + erff(v2 * 0.70710678118654752f));
                v3 = 0.5f * v3 * (1.0f + erff(v3 * 0.70710678118654752f));
            }
            Sf[r0 * 97 + nn] = v0;       Sf[r0 * 97 + nn + 1] = v1;
            Sf[(r0 + 8) * 97 + nn] = v2; Sf[(r0 + 8) * 97 + nn + 1] = v3;
        }
    }
    __syncthreads();

#pragma unroll
    for (int i = 0; i < 12; i++) {
        int idx = tid + (i << 8);
        int row = idx / 24, q4 = idx - row * 24;
        int m = m0 + row, n = n0 + (q4 << 2);
        float* sp = Sf + row * 97 + (q4 << 2);
        float4 v; v.x = sp[0]; v.y = sp[1]; v.z = sp[2]; v.w = sp[3];
        if (MODE == 0) {
            *(float4*)(g_QKV + (size_t)m * 288 + n) = v;
        } else if (MODE == 1) {
            int d0 = g_DST[m];
            float4 r = *(const float4*)(res + (size_t)d0 * 96 + n);
            v.x += r.x; v.y += r.y; v.z += r.z; v.w += r.w;
            *(float4*)(g_X + (size_t)d0 * 96 + n) = v;
            sp[0] = v.x; sp[1] = v.y; sp[2] = v.z; sp[3] = v.w;  // keep for LN2
        } else if (MODE == 2) {
            *(float4*)(g_FF + (size_t)m * 384 + n) = v;
        } else {
            float4 r = *(const float4*)(g_X + (size_t)m * 96 + n);
            v.x += r.x; v.y += r.y; v.z += r.z; v.w += r.w;
            *(float4*)(outp + (size_t)m * 96 + n) = v;
        }
    }

    if (MODE == 1) {
        __syncthreads();
        int row = tid >> 1, half = tid & 1;
        const float* rp = Sf + row * 97 + half * 48;
        float s = 0.f, ss = 0.f;
#pragma unroll
        for (int j = 0; j < 48; j++) {
            float v = rp[j];
            s += v; ss = fmaf(v, v, ss);
        }
        s  += __shfl_xor_sync(0xffffffffu, s, 1);
        ss += __shfl_xor_sync(0xffffffffu, ss, 1);
        float mean = s * (1.0f / 96.0f);
        float var  = ss * (1.0f / 96.0f) - mean * mean;
        float inv  = rsqrtf(var + 1e-5f);
        int d0 = g_DST[m0 + row];
        float* op = g_X2 + (size_t)d0 * 96 + half * 48;
#pragma unroll
        for (int j4 = 0; j4 < 12; j4++) {
            int n = half * 48 + j4 * 4;
            float4 o;
            o.x = (rp[j4 * 4]     - mean) * inv * __ldg(g2 + n)     + __ldg(b2 + n);
            o.y = (rp[j4 * 4 + 1] - mean) * inv * __ldg(g2 + n + 1) + __ldg(b2 + n + 1);
            o.z = (rp[j4 * 4 + 2] - mean) * inv * __ldg(g2 + n + 2) + __ldg(b2 + n + 2);
            o.w = (rp[j4 * 4 + 3] - mean) * inv * __ldg(g2 + n + 3) + __ldg(b2 + n + 3);
            *(float4*)(op + j4 * 4) = o;
        }
    }
}

// ---------------------------------------------------------------------------
// MMA attention: block = (window, head), 704 threads = 22 warps,
// warp owns 16 query rows (one m16 tile). Flash over key chunks of 32.
// Q fragments straight from gmem; K/V staged raw to smem.
// ---------------------------------------------------------------------------
#define NPAD 352
#define ASTRIDE 36
#define ATHREADS 704
#define ATTN_SMEM ((2 * NPAD * ASTRIDE + 2197 + NPAD) * 4)   // 111572 B

__global__ void __launch_bounds__(ATHREADS, 1) attn_mma(const float* __restrict__ rpb)
{
    extern __shared__ __align__(16) char smraw[];
    uint32_t* Ks = (uint32_t*)smraw;                          // [352][36]
    uint32_t* Vs = Ks + NPAD * ASTRIDE;
    float*    Bf = (float*)(Vs + NPAD * ASTRIDE);             // [2197]
    int*      Ms = (int*)(Bf + 2197);                         // [352]

    int w   = blockIdx.x / 3;
    int h   = blockIdx.x - w * 3;
    int tid = threadIdx.x;
    const float* base = g_QKV + (size_t)w * NTOK * 288;

    for (int i = tid; i < NTOK * 32; i += ATHREADS) {
        int n = i >> 5, j = i & 31;
        const float* bp = base + n * 288 + h * 32 + j;
        Ks[n * ASTRIDE + j] = __float_as_uint(bp[96]);
        Vs[n * ASTRIDE + j] = __float_as_uint(bp[192]);
    }
    for (int i = NTOK * 32 + tid; i < NPAD * 32; i += ATHREADS) {
        int n = i >> 5, j = i & 31;
        Ks[n * ASTRIDE + j] = 0;
        Vs[n * ASTRIDE + j] = 0;
    }
    for (int i = tid; i < 2197; i += ATHREADS)
        Bf[i] = rpb[i * 3 + h];

    int iH = w >> 5, iW = (w >> 2) & 7, iD = w & 3;
    for (int m = tid; m < NPAD; m += ATHREADS) {
        if (m < NTOK) {
            int a = m / 49; int r = m - a * 49; int b = r / 7; int c = r - b * 7;
            int sub = a * 169 + b * 13 + c;
            int ph = iH * 7 + a, pw = iW * 7 + b, pd = iD * 7 + c;
            int rh = (ph < 49) ? 0 : ((ph < 53) ? 1 : 2);
            int rw = (pw < 49) ? 0 : ((pw < 53) ? 1 : 2);
            int rd = (pd < 21) ? 0 : ((pd < 25) ? 1 : 2);
            Ms[m] = sub | (((rh * 3 + rw) * 3 + rd) << 16);
        } else {
            Ms[m] = 0;
        }
    }
    __syncthreads();

    int wid  = tid >> 5, lane = tid & 31;
    int g    = lane >> 2, c = lane & 3;
    int q0   = wid * 16;

    // Q fragments direct from gmem (row-clamped for padding rows)
    int r0 = q0 + g, r1 = q0 + 8 + g;
    int qr0 = (r0 < NTOK) ? r0 : NTOK - 1;
    int qr1 = (r1 < NTOK) ? r1 : NTOK - 1;
    const float* qp0 = base + qr0 * 288 + h * 32;
    const float* qp1 = base + qr1 * 288 + h * 32;
    uint32_t qa[4][4];
#pragma unroll
    for (int kk = 0; kk < 4; kk++) {
        int kc8 = kk * 8 + c;
        qa[kk][0] = __float_as_uint(qp0[kc8]);
        qa[kk][1] = __float_as_uint(qp1[kc8]);
        qa[kk][2] = __float_as_uint(qp0[kc8 + 4]);
        qa[kk][3] = __float_as_uint(qp1[kc8 + 4]);
    }

    int ibq[2], cnq[2];
    {
        int mv0 = Ms[r0], mv1 = Ms[r1];
        ibq[0] = (mv0 & 0xffff) + 1098; cnq[0] = mv0 >> 16;
        ibq[1] = (mv1 & 0xffff) + 1098; cnq[1] = mv1 >> 16;
    }

    float mrun[2] = {-1e30f, -1e30f};
    float lrun[2] = {0.f, 0.f};
    float o[4][4];
#pragma unroll
    for (int nb = 0; nb < 4; nb++)
#pragma unroll
        for (int j = 0; j < 4; j++) o[nb][j] = 0.f;

    for (int kc = 0; kc < NPAD; kc += 32) {
        int km[8];
#pragma unroll
        for (int nb = 0; nb < 4; nb++) {
#pragma unroll
            for (int e = 0; e < 2; e++)
                km[nb * 2 + e] = Ms[kc + nb * 8 + 2 * c + e];
        }

        float sa[4][4];
#pragma unroll
        for (int nb = 0; nb < 4; nb++)
#pragma unroll
            for (int j = 0; j < 4; j++) sa[nb][j] = 0.f;

#pragma unroll
        for (int nb = 0; nb < 4; nb++) {
            int krow = kc + nb * 8 + g;
#pragma unroll
            for (int kk = 0; kk < 4; kk++) {
                uint32_t b0 = Ks[krow * ASTRIDE + kk * 8 + c];
                uint32_t b1 = Ks[krow * ASTRIDE + kk * 8 + c + 4];
                mma8(sa[nb], qa[kk], b0, b1);
            }
        }

#pragma unroll
        for (int nb = 0; nb < 4; nb++) {
#pragma unroll
            for (int sl = 0; sl < 4; sl++) {
                int e  = sl & 1;
                int ri = sl >> 1;
                int j  = kc + nb * 8 + 2 * c + e;
                int kv = km[nb * 2 + e];
                float s = sa[nb][sl] + Bf[ibq[ri] - (kv & 0xffff)];
                if (cnq[ri] != (kv >> 16)) s -= 100.0f;
                if (j >= NTOK) s = -30000.0f;
                sa[nb][sl] = s;
            }
        }

#pragma unroll
        for (int ri = 0; ri < 2; ri++) {
            float mx = -3e4f;
#pragma unroll
            for (int nb = 0; nb < 4; nb++)
                mx = fmaxf(mx, fmaxf(sa[nb][ri * 2], sa[nb][ri * 2 + 1]));
            mx = fmaxf(mx, __shfl_xor_sync(0xffffffffu, mx, 1));
            mx = fmaxf(mx, __shfl_xor_sync(0xffffffffu, mx, 2));
            float mnew = fmaxf(mrun[ri], mx);
            float corr = __expf(mrun[ri] - mnew);
            mrun[ri] = mnew;
            float ls = 0.f;
#pragma unroll
            for (int nb = 0; nb < 4; nb++) {
                float p0 = __expf(sa[nb][ri * 2]     - mnew);
                float p1 = __expf(sa[nb][ri * 2 + 1] - mnew);
                sa[nb][ri * 2]     = p0;
                sa[nb][ri * 2 + 1] = p1;
                ls += p0 + p1;
            }
            ls += __shfl_xor_sync(0xffffffffu, ls, 1);
            ls += __shfl_xor_sync(0xffffffffu, ls, 2);
            lrun[ri] = lrun[ri] * corr + ls;
#pragma unroll
            for (int nb = 0; nb < 4; nb++) {
                o[nb][ri * 2]     *= corr;
                o[nb][ri * 2 + 1] *= corr;
            }
        }

        int src0 = (lane & ~3) | (c >> 1);
        int src1 = src0 + 2;
        int par  = c & 1;
#pragma unroll
        for (int kb = 0; kb < 4; kb++) {
            uint32_t ua[4];
            float v00 = __shfl_sync(0xffffffffu, sa[kb][0], src0);
            float v01 = __shfl_sync(0xffffffffu, sa[kb][1], src0);
            float v10 = __shfl_sync(0xffffffffu, sa[kb][2], src0);
            float v11 = __shfl_sync(0xffffffffu, sa[kb][3], src0);
            float w00 = __shfl_sync(0xffffffffu, sa[kb][0], src1);
            float w01 = __shfl_sync(0xffffffffu, sa[kb][1], src1);
            float w10 = __shfl_sync(0xffffffffu, sa[kb][2], src1);
            float w11 = __shfl_sync(0xffffffffu, sa[kb][3], src1);
            ua[0] = __float_as_uint(par ? v01 : v00);
            ua[1] = __float_as_uint(par ? v11 : v10);
            ua[2] = __float_as_uint(par ? w01 : w00);
            ua[3] = __float_as_uint(par ? w11 : w10);
            int vr0 = kc + kb * 8 + c;
#pragma unroll
            for (int nb = 0; nb < 4; nb++) {
                uint32_t b0 = Vs[vr0 * ASTRIDE + nb * 8 + g];
                uint32_t b1 = Vs[(vr0 + 4) * ASTRIDE + nb * 8 + g];
                mma8(o[nb], ua, b0, b1);
            }
        }
    }

    float inv0 = 1.0f / lrun[0];
    float inv1 = 1.0f / lrun[1];
    if (r0 < NTOK) {
        float* op = g_O + ((size_t)w * NTOK + r0) * CDIM + h * 32;
#pragma unroll
        for (int nb = 0; nb < 4; nb++) {
            float2 st; st.x = o[nb][0] * inv0; st.y = o[nb][1] * inv0;
            *(float2*)(op + nb * 8 + 2 * c) = st;
        }
    }
    if (r1 < NTOK) {
        float* op = g_O + ((size_t)w * NTOK + r1) * CDIM + h * 32;
#pragma unroll
        for (int nb = 0; nb < 4; nb++) {
            float2 st; st.x = o[nb][2] * inv1; st.y = o[nb][3] * inv1;
            *(float2*)(op + nb * 8 + 2 * c) = st;
        }
    }
}

// ---------------------------------------------------------------------------
// Launch
// ---------------------------------------------------------------------------
extern "C" void kernel_launch(void* const* d_in, const int* in_sizes, int n_in,
                              void* d_out, int out_size)
{
    const float* x      = (const float*)d_in[0];
    const float* n1g    = (const float*)d_in[1];
    const float* n1b    = (const float*)d_in[2];
    const float* qkv_w  = (const float*)d_in[3];
    const float* qkv_b  = (const float*)d_in[4];
    const float* rpb    = (const float*)d_in[5];
    const float* proj_w = (const float*)d_in[6];
    const float* proj_b = (const float*)d_in[7];
    const float* n2g    = (const float*)d_in[8];
    const float* n2b    = (const float*)d_in[9];
    const float* fc1_w  = (const float*)d_in[10];
    const float* fc1_b  = (const float*)d_in[11];
    const float* fc2_w  = (const float*)d_in[12];
    const float* fc2_b  = (const float*)d_in[13];
    float* out = (float*)d_out;

    cudaFuncSetAttribute(gemm_mma<0>, cudaFuncAttributeMaxDynamicSharedMemorySize, GEMM_SMEM);
    cudaFuncSetAttribute(gemm_mma<1>, cudaFuncAttributeMaxDynamicSharedMemorySize, GEMM_SMEM);
    cudaFuncSetAttribute(gemm_mma<2>, cudaFuncAttributeMaxDynamicSharedMemorySize, GEMM_SMEM);
    cudaFuncSetAttribute(gemm_mma<3>, cudaFuncAttributeMaxDynamicSharedMemorySize, GEMM_SMEM);
    cudaFuncSetAttribute(attn_mma, cudaFuncAttributeMaxDynamicSharedMemorySize, ATTN_SMEM);

    transpose_all<<<432, 256>>>(qkv_w, proj_w, fc1_w, fc2_w);

    ln_kernel<<<LTOK / 8, 256>>>(x, n1g, n1b);

    gemm_mma<0><<<dim3(3, 686), 256, GEMM_SMEM>>>(qkv_b, nullptr, nullptr, 96, nullptr, nullptr);

    attn_mma<<<NWIN * NHEAD, ATHREADS, ATTN_SMEM>>>(rpb);

    gemm_mma<1><<<dim3(1, 686), 256, GEMM_SMEM>>>(proj_b, x, nullptr, 96, n2g, n2b);

    gemm_mma<2><<<dim3(4, 686), 256, GEMM_SMEM>>>(fc1_b, nullptr, nullptr, 96, nullptr, nullptr);

    gemm_mma<3><<<dim3(1, 686), 256, GEMM_SMEM>>>(fc2_b, nullptr, out, 384, nullptr, nullptr);
}

// round 7
// speedup vs baseline: 1.0235x; 1.0235x over previous
#include <cuda_runtime.h>
#include <cstdint>

// ---------------------------------------------------------------------------
// Problem constants
// ---------------------------------------------------------------------------
#define HH   56
#define WWID 56
#define DDEP 28
#define LTOK 87808          // 56*56*28
#define CDIM 96
#define NWIN 256
#define NTOK 343
#define NHEAD 3
#define FF   384
#define BN   96             // GEMM N tile
#define BM   128            // GEMM M tile
#define KPAD 36             // smem row stride (floats)

// ---------------------------------------------------------------------------
// Scratch (device globals; no allocation allowed)
// ---------------------------------------------------------------------------
__device__ __align__(16) float g_H  [(size_t)LTOK * CDIM];
__device__ __align__(16) float g_QKV[(size_t)LTOK * 288];
__device__ __align__(16) float g_O  [(size_t)LTOK * CDIM];
__device__ __align__(16) float g_X  [(size_t)LTOK * CDIM];
__device__ __align__(16) float g_X2 [(size_t)LTOK * CDIM];
__device__ __align__(16) float g_FF [(size_t)LTOK * FF];
__device__ int g_DST[LTOK];
// pre-transposed weights [N,K]
__device__ __align__(16) float g_WtQKV [288 * 96];
__device__ __align__(16) float g_WtPROJ[96 * 96];
__device__ __align__(16) float g_WtFC1 [384 * 96];
__device__ __align__(16) float g_WtFC2 [96 * 384];
// precomputed bias+mask table: [8 classes][3 heads][343 rows][352 cols]
#define SBROW 352
__device__ __align__(16) float g_SB[24 * NTOK * SBROW];

// ---------------------------------------------------------------------------
// helpers
// ---------------------------------------------------------------------------
__device__ __forceinline__ void mma8(float* c, const uint32_t* a, uint32_t b0, uint32_t b1) {
    asm("mma.sync.aligned.m16n8k8.row.col.f32.tf32.tf32.f32 "
        "{%0,%1,%2,%3}, {%4,%5,%6,%7}, {%8,%9}, {%0,%1,%2,%3};"
        : "+f"(c[0]), "+f"(c[1]), "+f"(c[2]), "+f"(c[3])
        : "r"(a[0]), "r"(a[1]), "r"(a[2]), "r"(a[3]), "r"(b0), "r"(b1));
}

// ---------------------------------------------------------------------------
// Bias+mask table precompute: SB[cls][h][n][m]
// ---------------------------------------------------------------------------
__global__ void bias_precompute(const float* __restrict__ rpb)
{
    int gid = blockIdx.x * 256 + threadIdx.x;
    if (gid >= 24 * NTOK * SBROW) return;
    int m  = gid % SBROW;
    int t  = gid / SBROW;
    int n  = t % NTOK;
    int ch = t / NTOK;          // cls*3 + h
    int h  = ch % 3, cls = ch / 3;
    float v;
    if (m >= NTOK) {
        v = -30000.0f;
    } else {
        int an = n / 49, rn = n - an * 49, bn = rn / 7, cn = rn - bn * 7;
        int am = m / 49, rm = m - am * 49, bm = rm / 7, cm = rm - bm * 7;
        int sub_n = an * 169 + bn * 13 + cn;
        int sub_m = am * 169 + bm * 13 + cm;
        v = rpb[(1098 + sub_n - sub_m) * 3 + h];
        int bh = (cls >> 2) & 1, bw = (cls >> 1) & 1, bd = cls & 1;
        int rgn_n = ((bh ? (an < 4 ? 1 : 2) : 0) * 3 + (bw ? (bn < 4 ? 1 : 2) : 0)) * 3
                  + (bd ? (cn < 4 ? 1 : 2) : 0);
        int rgn_m = ((bh ? (am < 4 ? 1 : 2) : 0) * 3 + (bw ? (bm < 4 ? 1 : 2) : 0)) * 3
                  + (bd ? (cm < 4 ? 1 : 2) : 0);
        if (rgn_n != rgn_m) v -= 100.0f;
    }
    g_SB[gid] = v;
}

// ---------------------------------------------------------------------------
// LayerNorm #1 (one warp per token): gather + shift + window partition
// ---------------------------------------------------------------------------
__global__ void __launch_bounds__(256) ln_kernel(const float* __restrict__ in,
                                                 const float* __restrict__ gamma,
                                                 const float* __restrict__ beta)
{
    int gw   = (blockIdx.x * 256 + threadIdx.x) >> 5;
    int lane = threadIdx.x & 31;
    if (gw >= LTOK) return;

    int w = gw / NTOK, n = gw - w * NTOK;
    int iH = w >> 5, iW = (w >> 2) & 7, iD = w & 3;
    int a = n / 49; int r = n - a * 49; int b = r / 7; int c = r - b * 7;
    int th = iH * 7 + a + 3; if (th >= HH)   th -= HH;
    int tw = iW * 7 + b + 3; if (tw >= WWID) tw -= WWID;
    int td = iD * 7 + c + 3; if (td >= DDEP) td -= DDEP;
    int src = (th * WWID + tw) * DDEP + td;
    if (lane == 0) g_DST[gw] = src;
    const float* inp  = in + (size_t)src * CDIM;
    float* outp = g_H + (size_t)gw * CDIM;

    float v0 = inp[lane], v1 = inp[lane + 32], v2 = inp[lane + 64];
    float s  = v0 + v1 + v2;
    float ss = fmaf(v0, v0, fmaf(v1, v1, v2 * v2));
#pragma unroll
    for (int o = 16; o; o >>= 1) {
        s  += __shfl_xor_sync(0xffffffffu, s, o);
        ss += __shfl_xor_sync(0xffffffffu, ss, o);
    }
    float mean = s * (1.0f / 96.0f);
    float var  = ss * (1.0f / 96.0f) - mean * mean;
    float inv  = rsqrtf(var + 1e-5f);
    outp[lane]      = (v0 - mean) * inv * gamma[lane]      + beta[lane];
    outp[lane + 32] = (v1 - mean) * inv * gamma[lane + 32] + beta[lane + 32];
    outp[lane + 64] = (v2 - mean) * inv * gamma[lane + 64] + beta[lane + 64];
}

// ---------------------------------------------------------------------------
// All weight transposes in one launch: W[K,N] -> Wt[N,K]
// ---------------------------------------------------------------------------
__global__ void transpose_all(const float* __restrict__ qkv_w,
                              const float* __restrict__ proj_w,
                              const float* __restrict__ fc1_w,
                              const float* __restrict__ fc2_w)
{
    int idx = blockIdx.x * 256 + threadIdx.x;
    if (idx < 27648) {
        int k = idx / 288, n = idx - k * 288;
        g_WtQKV[n * 96 + k] = qkv_w[idx];
    } else if (idx < 36864) {
        int j = idx - 27648;
        int k = j / 96, n = j - k * 96;
        g_WtPROJ[n * 96 + k] = proj_w[j];
    } else if (idx < 73728) {
        int j = idx - 36864;
        int k = j / 384, n = j - k * 384;
        g_WtFC1[n * 96 + k] = fc1_w[j];
    } else if (idx < 110592) {
        int j = idx - 73728;
        int k = j / 96, n = j - k * 96;
        g_WtFC2[n * 384 + k] = fc2_w[j];
    }
}

// ---------------------------------------------------------------------------
// Double-buffered mma.sync tf32 GEMM: C[128,96] = A[128,K] @ Wt[96,K]^T
// MODE 0: qkv (q-scale)  MODE 1: proj (scatter+residual + fused LN2)
// MODE 2: fc1 (GELU)     MODE 3: fc2 (+residual -> d_out)
// ---------------------------------------------------------------------------
#define ABUF 4608
#define BBUF 3456
#define GEMM_SMEM ((2 * ABUF + 2 * BBUF) * 4)

template <int MODE>
__global__ void __launch_bounds__(256) gemm_mma(const float* __restrict__ bias,
                                                const float* __restrict__ res,
                                                float* __restrict__ outp,
                                                int K,
                                                const float* __restrict__ g2,
                                                const float* __restrict__ b2)
{
    extern __shared__ __align__(16) char smraw[];
    uint32_t* Au = (uint32_t*)smraw;
    uint32_t* Bu = (uint32_t*)(smraw + 2 * ABUF * 4);
    float*    Sf = (float*)smraw;

    const float* A  = (MODE == 0) ? g_H : (MODE == 1) ? g_O : (MODE == 2) ? g_X2 : g_FF;
    const float* Wt = (MODE == 0) ? g_WtQKV : (MODE == 1) ? g_WtPROJ
                    : (MODE == 2) ? g_WtFC1 : g_WtFC2;

    int tid  = threadIdx.x;
    int wid  = tid >> 5, lane = tid & 31;
    int wr   = wid >> 1, wc = wid & 1;
    int g    = lane >> 2, c = lane & 3;
    int m0   = blockIdx.y * BM;
    int n0   = blockIdx.x * BN;

    int arow = tid >> 3, aq = (tid & 7) << 2;
    const float* Aptr = A + (size_t)(m0 + arow) * K + aq;
    int brow = tid >> 3;
    const float* Bptr = Wt + (size_t)(n0 + brow) * K + aq;

    float4 ra[4], rb[3];
#pragma unroll
    for (int i = 0; i < 4; i++)
        ra[i] = *(const float4*)(Aptr + (size_t)(i << 5) * K);
#pragma unroll
    for (int i = 0; i < 3; i++)
        rb[i] = *(const float4*)(Bptr + (size_t)(i << 5) * K);

    auto stage = [&](int b) {
        uint32_t* Ad = Au + b * ABUF;
        uint32_t* Bd = Bu + b * BBUF;
#pragma unroll
        for (int i = 0; i < 4; i++)
            *(float4*)(Ad + (arow + (i << 5)) * KPAD + aq) = ra[i];
#pragma unroll
        for (int i = 0; i < 3; i++)
            *(float4*)(Bd + (brow + (i << 5)) * KPAD + aq) = rb[i];
    };

    stage(0);
    __syncthreads();

    float acc[2][6][4];
#pragma unroll
    for (int t = 0; t < 2; t++)
#pragma unroll
        for (int u = 0; u < 6; u++)
#pragma unroll
            for (int j = 0; j < 4; j++) acc[t][u][j] = 0.0f;

    int nc = K >> 5;
    for (int ch = 0; ch < nc; ch++) {
        if (ch + 1 < nc) {
            int k1 = (ch + 1) << 5;
#pragma unroll
            for (int i = 0; i < 4; i++)
                ra[i] = *(const float4*)(Aptr + (size_t)(i << 5) * K + k1);
#pragma unroll
            for (int i = 0; i < 3; i++)
                rb[i] = *(const float4*)(Bptr + (size_t)(i << 5) * K + k1);
        }
        const uint32_t* As = Au + (ch & 1) * ABUF;
        const uint32_t* Bs = Bu + (ch & 1) * BBUF;
#pragma unroll
        for (int ks = 0; ks < 4; ks++) {
            int kk = (ks << 3) + c;
            uint32_t a[2][4];
#pragma unroll
            for (int t = 0; t < 2; t++) {
                int r0 = wr * 32 + t * 16 + g;
                a[t][0] = As[r0 * KPAD + kk];
                a[t][1] = As[(r0 + 8) * KPAD + kk];
                a[t][2] = As[r0 * KPAD + kk + 4];
                a[t][3] = As[(r0 + 8) * KPAD + kk + 4];
            }
#pragma unroll
            for (int u = 0; u < 6; u++) {
                int nb = wc * 48 + u * 8 + g;
                uint32_t b0 = Bs[nb * KPAD + kk];
                uint32_t b1 = Bs[nb * KPAD + kk + 4];
                mma8(acc[0][u], a[0], b0, b1);
                mma8(acc[1][u], a[1], b0, b1);
            }
        }
        if (ch + 1 < nc) {
            stage((ch + 1) & 1);
            __syncthreads();
        }
    }
    __syncthreads();

#pragma unroll
    for (int t = 0; t < 2; t++) {
#pragma unroll
        for (int u = 0; u < 6; u++) {
            int r0 = wr * 32 + t * 16 + g;
            int nn = wc * 48 + u * 8 + 2 * c;
            float b0 = __ldg(bias + n0 + nn);
            float b1 = __ldg(bias + n0 + nn + 1);
            float v0 = acc[t][u][0] + b0, v1 = acc[t][u][1] + b1;
            float v2 = acc[t][u][2] + b0, v3 = acc[t][u][3] + b1;
            if (MODE == 0 && n0 == 0) {
                v0 *= 0.17677669529663689f; v1 *= 0.17677669529663689f;
                v2 *= 0.17677669529663689f; v3 *= 0.17677669529663689f;
            }
            if (MODE == 2) {
                v0 = 0.5f * v0 * (1.0f + erff(v0 * 0.70710678118654752f));
                v1 = 0.5f * v1 * (1.0f + erff(v1 * 0.70710678118654752f));
                v2 = 0.5f * v2 * (1.0f + erff(v2 * 0.70710678118654752f));
                v3 = 0.5f * v3 * (1.0f + erff(v3 * 0.70710678118654752f));
            }
            Sf[r0 * 97 + nn] = v0;       Sf[r0 * 97 + nn + 1] = v1;
            Sf[(r0 + 8) * 97 + nn] = v2; Sf[(r0 + 8) * 97 + nn + 1] = v3;
        }
    }
    __syncthreads();

#pragma unroll
    for (int i = 0; i < 12; i++) {
        int idx = tid + (i << 8);
        int row = idx / 24, q4 = idx - row * 24;
        int m = m0 + row, n = n0 + (q4 << 2);
        float* sp = Sf + row * 97 + (q4 << 2);
        float4 v; v.x = sp[0]; v.y = sp[1]; v.z = sp[2]; v.w = sp[3];
        if (MODE == 0) {
            *(float4*)(g_QKV + (size_t)m * 288 + n) = v;
        } else if (MODE == 1) {
            int d0 = g_DST[m];
            float4 r = *(const float4*)(res + (size_t)d0 * 96 + n);
            v.x += r.x; v.y += r.y; v.z += r.z; v.w += r.w;
            *(float4*)(g_X + (size_t)d0 * 96 + n) = v;
            sp[0] = v.x; sp[1] = v.y; sp[2] = v.z; sp[3] = v.w;
        } else if (MODE == 2) {
            *(float4*)(g_FF + (size_t)m * 384 + n) = v;
        } else {
            float4 r = *(const float4*)(g_X + (size_t)m * 96 + n);
            v.x += r.x; v.y += r.y; v.z += r.z; v.w += r.w;
            *(float4*)(outp + (size_t)m * 96 + n) = v;
        }
    }

    if (MODE == 1) {
        __syncthreads();
        int row = tid >> 1, half = tid & 1;
        const float* rp = Sf + row * 97 + half * 48;
        float s = 0.f, ss = 0.f;
#pragma unroll
        for (int j = 0; j < 48; j++) {
            float v = rp[j];
            s += v; ss = fmaf(v, v, ss);
        }
        s  += __shfl_xor_sync(0xffffffffu, s, 1);
        ss += __shfl_xor_sync(0xffffffffu, ss, 1);
        float mean = s * (1.0f / 96.0f);
        float var  = ss * (1.0f / 96.0f) - mean * mean;
        float inv  = rsqrtf(var + 1e-5f);
        int d0 = g_DST[m0 + row];
        float* op = g_X2 + (size_t)d0 * 96 + half * 48;
#pragma unroll
        for (int j4 = 0; j4 < 12; j4++) {
            int n = half * 48 + j4 * 4;
            float4 o;
            o.x = (rp[j4 * 4]     - mean) * inv * __ldg(g2 + n)     + __ldg(b2 + n);
            o.y = (rp[j4 * 4 + 1] - mean) * inv * __ldg(g2 + n + 1) + __ldg(b2 + n + 1);
            o.z = (rp[j4 * 4 + 2] - mean) * inv * __ldg(g2 + n + 2) + __ldg(b2 + n + 2);
            o.w = (rp[j4 * 4 + 3] - mean) * inv * __ldg(g2 + n + 3) + __ldg(b2 + n + 3);
            *(float4*)(op + j4 * 4) = o;
        }
    }
}

// ---------------------------------------------------------------------------
// MMA attention: block = (window, head), 352 threads = 11 warps,
// warp owns 32 query rows (2 m16 tiles). Flash over key chunks of 32.
// Bias+mask from precomputed g_SB table (float2 per score pair).
// ---------------------------------------------------------------------------
#define NPAD 352
#define ASTRIDE 36
#define ATTN_SMEM (2 * NPAD * ASTRIDE * 4)   // K + V = 101376 B

__global__ void __launch_bounds__(352, 1) attn_mma(const float* __restrict__ rpb)
{
    extern __shared__ __align__(16) char smraw[];
    uint32_t* Ks = (uint32_t*)smraw;                          // [352][36]
    uint32_t* Vs = Ks + NPAD * ASTRIDE;

    int w   = blockIdx.x / 3;
    int h   = blockIdx.x - w * 3;
    int tid = threadIdx.x;
    const float* base = g_QKV + (size_t)w * NTOK * 288;

    for (int i = tid; i < NTOK * 32; i += 352) {
        int n = i >> 5, j = i & 31;
        const float* bp = base + n * 288 + h * 32 + j;
        Ks[n * ASTRIDE + j] = __float_as_uint(bp[96]);
        Vs[n * ASTRIDE + j] = __float_as_uint(bp[192]);
    }
    for (int i = NTOK * 32 + tid; i < NPAD * 32; i += 352) {
        int n = i >> 5, j = i & 31;
        Ks[n * ASTRIDE + j] = 0;
        Vs[n * ASTRIDE + j] = 0;
    }
    __syncthreads();

    int wid  = tid >> 5, lane = tid & 31;
    int g    = lane >> 2, c = lane & 3;
    int q0   = wid * 32;

    int iH = w >> 5, iW = (w >> 2) & 7, iD = w & 3;
    int cls = ((iH == 7) << 2) | ((iW == 7) << 1) | (iD == 3);
    const float* SB = g_SB + (size_t)(cls * 3 + h) * NTOK * SBROW;

    // Q fragments direct from gmem; per-row bias pointers (row-clamped)
    uint32_t qa[2][4][4];
    const float* sbp[4];
#pragma unroll
    for (int t = 0; t < 2; t++) {
#pragma unroll
        for (int rr = 0; rr < 2; rr++) {
            int row = q0 + t * 16 + rr * 8 + g;
            int rc  = (row < NTOK) ? row : NTOK - 1;
            sbp[t * 2 + rr] = SB + (size_t)rc * SBROW;
            const float* qp = base + rc * 288 + h * 32;
#pragma unroll
            for (int kk = 0; kk < 4; kk++) {
                qa[t][kk][rr]     = __float_as_uint(qp[kk * 8 + c]);
                qa[t][kk][rr + 2] = __float_as_uint(qp[kk * 8 + c + 4]);
            }
        }
    }

    float mrun[4] = {-1e30f, -1e30f, -1e30f, -1e30f};
    float lrun[4] = {0.f, 0.f, 0.f, 0.f};
    float o[2][4][4];
#pragma unroll
    for (int t = 0; t < 2; t++)
#pragma unroll
        for (int nb = 0; nb < 4; nb++)
#pragma unroll
            for (int j = 0; j < 4; j++) o[t][nb][j] = 0.f;

    for (int kc = 0; kc < NPAD; kc += 32) {
        float sa[2][4][4];
#pragma unroll
        for (int t = 0; t < 2; t++)
#pragma unroll
            for (int nb = 0; nb < 4; nb++)
#pragma unroll
                for (int j = 0; j < 4; j++) sa[t][nb][j] = 0.f;

#pragma unroll
        for (int nb = 0; nb < 4; nb++) {
            int krow = kc + nb * 8 + g;
#pragma unroll
            for (int kk = 0; kk < 4; kk++) {
                uint32_t b0 = Ks[krow * ASTRIDE + kk * 8 + c];
                uint32_t b1 = Ks[krow * ASTRIDE + kk * 8 + c + 4];
                mma8(sa[0][nb], qa[0][kk], b0, b1);
                mma8(sa[1][nb], qa[1][kk], b0, b1);
            }
        }

        // bias + mask + padding: one float2 per score pair from the table
#pragma unroll
        for (int t = 0; t < 2; t++) {
#pragma unroll
            for (int nb = 0; nb < 4; nb++) {
                int coff = kc + nb * 8 + 2 * c;
                float2 bv0 = *(const float2*)(sbp[t * 2]     + coff);
                float2 bv1 = *(const float2*)(sbp[t * 2 + 1] + coff);
                sa[t][nb][0] += bv0.x; sa[t][nb][1] += bv0.y;
                sa[t][nb][2] += bv1.x; sa[t][nb][3] += bv1.y;
            }
        }

#pragma unroll
        for (int ri = 0; ri < 4; ri++) {
            int t = ri >> 1, rr = ri & 1;
            float mx = -3e4f;
#pragma unroll
            for (int nb = 0; nb < 4; nb++)
                mx = fmaxf(mx, fmaxf(sa[t][nb][rr * 2], sa[t][nb][rr * 2 + 1]));
            mx = fmaxf(mx, __shfl_xor_sync(0xffffffffu, mx, 1));
            mx = fmaxf(mx, __shfl_xor_sync(0xffffffffu, mx, 2));
            float mnew = fmaxf(mrun[ri], mx);
            float corr = __expf(mrun[ri] - mnew);
            mrun[ri] = mnew;
            float ls = 0.f;
#pragma unroll
            for (int nb = 0; nb < 4; nb++) {
                float p0 = __expf(sa[t][nb][rr * 2]     - mnew);
                float p1 = __expf(sa[t][nb][rr * 2 + 1] - mnew);
                sa[t][nb][rr * 2]     = p0;
                sa[t][nb][rr * 2 + 1] = p1;
                ls += p0 + p1;
            }
            ls += __shfl_xor_sync(0xffffffffu, ls, 1);
            ls += __shfl_xor_sync(0xffffffffu, ls, 2);
            lrun[ri] = lrun[ri] * corr + ls;
#pragma unroll
            for (int nb = 0; nb < 4; nb++) {
                o[t][nb][rr * 2]     *= corr;
                o[t][nb][rr * 2 + 1] *= corr;
            }
        }

        int src0 = (lane & ~3) | (c >> 1);
        int src1 = src0 + 2;
        int par  = c & 1;
#pragma unroll
        for (int kb = 0; kb < 4; kb++) {
            uint32_t ua[2][4];
#pragma unroll
            for (int t = 0; t < 2; t++) {
                float v00 = __shfl_sync(0xffffffffu, sa[t][kb][0], src0);
                float v01 = __shfl_sync(0xffffffffu, sa[t][kb][1], src0);
                float v10 = __shfl_sync(0xffffffffu, sa[t][kb][2], src0);
                float v11 = __shfl_sync(0xffffffffu, sa[t][kb][3], src0);
                float w00 = __shfl_sync(0xffffffffu, sa[t][kb][0], src1);
                float w01 = __shfl_sync(0xffffffffu, sa[t][kb][1], src1);
                float w10 = __shfl_sync(0xffffffffu, sa[t][kb][2], src1);
                float w11 = __shfl_sync(0xffffffffu, sa[t][kb][3], src1);
                ua[t][0] = __float_as_uint(par ? v01 : v00);
                ua[t][1] = __float_as_uint(par ? v11 : v10);
                ua[t][2] = __float_as_uint(par ? w01 : w00);
                ua[t][3] = __float_as_uint(par ? w11 : w10);
            }
            int vr0 = kc + kb * 8 + c;
#pragma unroll
            for (int nb = 0; nb < 4; nb++) {
                uint32_t b0 = Vs[vr0 * ASTRIDE + nb * 8 + g];
                uint32_t b1 = Vs[(vr0 + 4) * ASTRIDE + nb * 8 + g];
                mma8(o[0][nb], ua[0], b0, b1);
                mma8(o[1][nb], ua[1], b0, b1);
            }
        }
    }

    float inv[4];
#pragma unroll
    for (int ri = 0; ri < 4; ri++) inv[ri] = 1.0f / lrun[ri];

#pragma unroll
    for (int t = 0; t < 2; t++) {
        int r0 = q0 + t * 16 + g;
#pragma unroll
        for (int rr = 0; rr < 2; rr++) {
            int row = r0 + rr * 8;
            if (row < NTOK) {
                int ri = t * 2 + rr;
                float* op = g_O + ((size_t)w * NTOK + row) * CDIM + h * 32;
#pragma unroll
                for (int nb = 0; nb < 4; nb++) {
                    float2 st;
                    st.x = o[t][nb][rr * 2]     * inv[ri];
                    st.y = o[t][nb][rr * 2 + 1] * inv[ri];
                    *(float2*)(op + nb * 8 + 2 * c) = st;
                }
            }
        }
    }
}

// ---------------------------------------------------------------------------
// Launch
// ---------------------------------------------------------------------------
extern "C" void kernel_launch(void* const* d_in, const int* in_sizes, int n_in,
                              void* d_out, int out_size)
{
    const float* x      = (const float*)d_in[0];
    const float* n1g    = (const float*)d_in[1];
    const float* n1b    = (const float*)d_in[2];
    const float* qkv_w  = (const float*)d_in[3];
    const float* qkv_b  = (const float*)d_in[4];
    const float* rpb    = (const float*)d_in[5];
    const float* proj_w = (const float*)d_in[6];
    const float* proj_b = (const float*)d_in[7];
    const float* n2g    = (const float*)d_in[8];
    const float* n2b    = (const float*)d_in[9];
    const float* fc1_w  = (const float*)d_in[10];
    const float* fc1_b  = (const float*)d_in[11];
    const float* fc2_w  = (const float*)d_in[12];
    const float* fc2_b  = (const float*)d_in[13];
    float* out = (float*)d_out;

    cudaFuncSetAttribute(gemm_mma<0>, cudaFuncAttributeMaxDynamicSharedMemorySize, GEMM_SMEM);
    cudaFuncSetAttribute(gemm_mma<1>, cudaFuncAttributeMaxDynamicSharedMemorySize, GEMM_SMEM);
    cudaFuncSetAttribute(gemm_mma<2>, cudaFuncAttributeMaxDynamicSharedMemorySize, GEMM_SMEM);
    cudaFuncSetAttribute(gemm_mma<3>, cudaFuncAttributeMaxDynamicSharedMemorySize, GEMM_SMEM);
    cudaFuncSetAttribute(attn_mma, cudaFuncAttributeMaxDynamicSharedMemorySize, ATTN_SMEM);

    transpose_all<<<432, 256>>>(qkv_w, proj_w, fc1_w, fc2_w);
    bias_precompute<<<(24 * NTOK * SBROW + 255) / 256, 256>>>(rpb);

    ln_kernel<<<LTOK / 8, 256>>>(x, n1g, n1b);

    gemm_mma<0><<<dim3(3, 686), 256, GEMM_SMEM>>>(qkv_b, nullptr, nullptr, 96, nullptr, nullptr);

    attn_mma<<<NWIN * NHEAD, 352, ATTN_SMEM>>>(rpb);

    gemm_mma<1><<<dim3(1, 686), 256, GEMM_SMEM>>>(proj_b, x, nullptr, 96, n2g, n2b);

    gemm_mma<2><<<dim3(4, 686), 256, GEMM_SMEM>>>(fc1_b, nullptr, nullptr, 96, nullptr, nullptr);

    gemm_mma<3><<<dim3(1, 686), 256, GEMM_SMEM>>>(fc2_b, nullptr, out, 384, nullptr, nullptr);
}

// round 8
// speedup vs baseline: 1.0765x; 1.0517x over previous
#include <cuda_runtime.h>
#include <cstdint>

// ---------------------------------------------------------------------------
// Problem constants
// ---------------------------------------------------------------------------
#define HH   56
#define WWID 56
#define DDEP 28
#define LTOK 87808          // 56*56*28
#define CDIM 96
#define NWIN 256
#define NTOK 343
#define NHEAD 3
#define FF   384
#define BN   96             // GEMM N tile
#define BM   128            // GEMM M tile

// ---------------------------------------------------------------------------
// Scratch (device globals; no allocation allowed)
// ---------------------------------------------------------------------------
__device__ __align__(16) float g_H  [(size_t)LTOK * CDIM];
__device__ __align__(16) float g_QKV[(size_t)LTOK * 288];
__device__ __align__(16) float g_O  [(size_t)LTOK * CDIM];
__device__ __align__(16) float g_X  [(size_t)LTOK * CDIM];
__device__ __align__(16) float g_X2 [(size_t)LTOK * CDIM];
__device__ __align__(16) float g_FF [(size_t)LTOK * FF];
__device__ int g_DST[LTOK];
// pre-transposed weights [N,K]
__device__ __align__(16) float g_WtQKV [288 * 96];
__device__ __align__(16) float g_WtPROJ[96 * 96];
__device__ __align__(16) float g_WtFC1 [384 * 96];
__device__ __align__(16) float g_WtFC2 [96 * 384];
// precomputed bias+mask table: [8 classes][3 heads][343 rows][352 cols]
#define SBROW 352
__device__ __align__(16) float g_SB[24 * NTOK * SBROW];

// ---------------------------------------------------------------------------
// helpers
// ---------------------------------------------------------------------------
__device__ __forceinline__ void mma8(float* c, const uint32_t* a, uint32_t b0, uint32_t b1) {
    asm("mma.sync.aligned.m16n8k8.row.col.f32.tf32.tf32.f32 "
        "{%0,%1,%2,%3}, {%4,%5,%6,%7}, {%8,%9}, {%0,%1,%2,%3};"
        : "+f"(c[0]), "+f"(c[1]), "+f"(c[2]), "+f"(c[3])
        : "r"(a[0]), "r"(a[1]), "r"(a[2]), "r"(a[3]), "r"(b0), "r"(b1));
}
__device__ __forceinline__ void mma16(float* c, const uint32_t* a, uint32_t b0, uint32_t b1) {
    asm("mma.sync.aligned.m16n8k16.row.col.f32.bf16.bf16.f32 "
        "{%0,%1,%2,%3}, {%4,%5,%6,%7}, {%8,%9}, {%0,%1,%2,%3};"
        : "+f"(c[0]), "+f"(c[1]), "+f"(c[2]), "+f"(c[3])
        : "r"(a[0]), "r"(a[1]), "r"(a[2]), "r"(a[3]), "r"(b0), "r"(b1));
}
__device__ __forceinline__ void ldsm4(uint32_t& r0, uint32_t& r1, uint32_t& r2, uint32_t& r3,
                                      uint32_t addr) {
    asm volatile("ldmatrix.sync.aligned.m8n8.x4.shared.b16 {%0,%1,%2,%3}, [%4];"
        : "=r"(r0), "=r"(r1), "=r"(r2), "=r"(r3) : "r"(addr));
}
__device__ __forceinline__ uint32_t bf2(float lo, float hi) {
    uint32_t d;
    asm("cvt.rn.bf16x2.f32 %0, %1, %2;" : "=r"(d) : "f"(hi), "f"(lo));
    return d;
}

// ---------------------------------------------------------------------------
// Bias+mask table precompute: SB[cls][h][n][m]
// ---------------------------------------------------------------------------
__global__ void bias_precompute(const float* __restrict__ rpb)
{
    int gid = blockIdx.x * 256 + threadIdx.x;
    if (gid >= 24 * NTOK * SBROW) return;
    int m  = gid % SBROW;
    int t  = gid / SBROW;
    int n  = t % NTOK;
    int ch = t / NTOK;
    int h  = ch % 3, cls = ch / 3;
    float v;
    if (m >= NTOK) {
        v = -30000.0f;
    } else {
        int an = n / 49, rn = n - an * 49, bn = rn / 7, cn = rn - bn * 7;
        int am = m / 49, rm = m - am * 49, bm = rm / 7, cm = rm - bm * 7;
        int sub_n = an * 169 + bn * 13 + cn;
        int sub_m = am * 169 + bm * 13 + cm;
        v = rpb[(1098 + sub_n - sub_m) * 3 + h];
        int bh = (cls >> 2) & 1, bw = (cls >> 1) & 1, bd = cls & 1;
        int rgn_n = ((bh ? (an < 4 ? 1 : 2) : 0) * 3 + (bw ? (bn < 4 ? 1 : 2) : 0)) * 3
                  + (bd ? (cn < 4 ? 1 : 2) : 0);
        int rgn_m = ((bh ? (am < 4 ? 1 : 2) : 0) * 3 + (bw ? (bm < 4 ? 1 : 2) : 0)) * 3
                  + (bd ? (cm < 4 ? 1 : 2) : 0);
        if (rgn_n != rgn_m) v -= 100.0f;
    }
    g_SB[gid] = v;
}

// ---------------------------------------------------------------------------
// LayerNorm #1 (one warp per token): gather + shift + window partition
// ---------------------------------------------------------------------------
__global__ void __launch_bounds__(256) ln_kernel(const float* __restrict__ in,
                                                 const float* __restrict__ gamma,
                                                 const float* __restrict__ beta)
{
    int gw   = (blockIdx.x * 256 + threadIdx.x) >> 5;
    int lane = threadIdx.x & 31;
    if (gw >= LTOK) return;

    int w = gw / NTOK, n = gw - w * NTOK;
    int iH = w >> 5, iW = (w >> 2) & 7, iD = w & 3;
    int a = n / 49; int r = n - a * 49; int b = r / 7; int c = r - b * 7;
    int th = iH * 7 + a + 3; if (th >= HH)   th -= HH;
    int tw = iW * 7 + b + 3; if (tw >= WWID) tw -= WWID;
    int td = iD * 7 + c + 3; if (td >= DDEP) td -= DDEP;
    int src = (th * WWID + tw) * DDEP + td;
    if (lane == 0) g_DST[gw] = src;
    const float* inp  = in + (size_t)src * CDIM;
    float* outp = g_H + (size_t)gw * CDIM;

    float v0 = inp[lane], v1 = inp[lane + 32], v2 = inp[lane + 64];
    float s  = v0 + v1 + v2;
    float ss = fmaf(v0, v0, fmaf(v1, v1, v2 * v2));
#pragma unroll
    for (int o = 16; o; o >>= 1) {
        s  += __shfl_xor_sync(0xffffffffu, s, o);
        ss += __shfl_xor_sync(0xffffffffu, ss, o);
    }
    float mean = s * (1.0f / 96.0f);
    float var  = ss * (1.0f / 96.0f) - mean * mean;
    float inv  = rsqrtf(var + 1e-5f);
    outp[lane]      = (v0 - mean) * inv * gamma[lane]      + beta[lane];
    outp[lane + 32] = (v1 - mean) * inv * gamma[lane + 32] + beta[lane + 32];
    outp[lane + 64] = (v2 - mean) * inv * gamma[lane + 64] + beta[lane + 64];
}

// ---------------------------------------------------------------------------
// All weight transposes in one launch: W[K,N] -> Wt[N,K]
// ---------------------------------------------------------------------------
__global__ void transpose_all(const float* __restrict__ qkv_w,
                              const float* __restrict__ proj_w,
                              const float* __restrict__ fc1_w,
                              const float* __restrict__ fc2_w)
{
    int idx = blockIdx.x * 256 + threadIdx.x;
    if (idx < 27648) {
        int k = idx / 288, n = idx - k * 288;
        g_WtQKV[n * 96 + k] = qkv_w[idx];
    } else if (idx < 36864) {
        int j = idx - 27648;
        int k = j / 96, n = j - k * 96;
        g_WtPROJ[n * 96 + k] = proj_w[j];
    } else if (idx < 73728) {
        int j = idx - 36864;
        int k = j / 384, n = j - k * 384;
        g_WtFC1[n * 96 + k] = fc1_w[j];
    } else if (idx < 110592) {
        int j = idx - 73728;
        int k = j / 96, n = j - k * 96;
        g_WtFC2[n * 384 + k] = fc2_w[j];
    }
}

// ---------------------------------------------------------------------------
// Double-buffered bf16 mma GEMM: C[128,96] = A[128,K] @ Wt[96,K]^T
// bf16 operands in smem (KPAD2=40 b16, LDSM bank-perfect), ldmatrix.x4
// fragment loads, m16n8k16 mma, fp32 accumulate.
// MODE 0: qkv (q-scale)  MODE 1: proj (scatter+residual + fused LN2)
// MODE 2: fc1 (GELU)     MODE 3: fc2 (+residual -> d_out)
// ---------------------------------------------------------------------------
#define KPAD2 40
#define A_BYTES (128 * KPAD2 * 2)     // 10240
#define B_BYTES (96 * KPAD2 * 2)      // 7680
#define B_OFF   (2 * A_BYTES)         // 20480
#define GEMM_SMEM 49664               // epilogue 128*97*4 dominates (mainloop 35840)

template <int MODE>
__global__ void __launch_bounds__(256) gemm_mma(const float* __restrict__ bias,
                                                const float* __restrict__ res,
                                                float* __restrict__ outp,
                                                int K,
                                                const float* __restrict__ g2,
                                                const float* __restrict__ b2)
{
    extern __shared__ __align__(16) char smraw[];
    float* Sf = (float*)smraw;   // epilogue staging [128][97]

    const float* A  = (MODE == 0) ? g_H : (MODE == 1) ? g_O : (MODE == 2) ? g_X2 : g_FF;
    const float* Wt = (MODE == 0) ? g_WtQKV : (MODE == 1) ? g_WtPROJ
                    : (MODE == 2) ? g_WtFC1 : g_WtFC2;

    int tid  = threadIdx.x;
    int wid  = tid >> 5, lane = tid & 31;
    int wr   = wid >> 1, wc = wid & 1;
    int g    = lane >> 2, c = lane & 3;
    int m0   = blockIdx.y * BM;
    int n0   = blockIdx.x * BN;

    uint32_t smem_base = (uint32_t)__cvta_generic_to_shared(smraw);

    int arow = tid >> 3, aq = (tid & 7) << 2;
    const float* Aptr = A + (size_t)(m0 + arow) * K + aq;
    const float* Bptr = Wt + (size_t)(n0 + arow) * K + aq;

    float4 ra[4], rb[3];
#pragma unroll
    for (int i = 0; i < 4; i++)
        ra[i] = *(const float4*)(Aptr + (size_t)(i << 5) * K);
#pragma unroll
    for (int i = 0; i < 3; i++)
        rb[i] = *(const float4*)(Bptr + (size_t)(i << 5) * K);

    auto stage = [&](int b) {
        uint16_t* Ad = (uint16_t*)(smraw + b * A_BYTES);
        uint16_t* Bd = (uint16_t*)(smraw + B_OFF + b * B_BYTES);
#pragma unroll
        for (int i = 0; i < 4; i++) {
            uint2 u;
            u.x = bf2(ra[i].x, ra[i].y);
            u.y = bf2(ra[i].z, ra[i].w);
            *(uint2*)(Ad + (arow + (i << 5)) * KPAD2 + aq) = u;
        }
#pragma unroll
        for (int i = 0; i < 3; i++) {
            uint2 u;
            u.x = bf2(rb[i].x, rb[i].y);
            u.y = bf2(rb[i].z, rb[i].w);
            *(uint2*)(Bd + (arow + (i << 5)) * KPAD2 + aq) = u;
        }
    };

    stage(0);
    __syncthreads();

    float acc[2][6][4];
#pragma unroll
    for (int t = 0; t < 2; t++)
#pragma unroll
        for (int u = 0; u < 6; u++)
#pragma unroll
            for (int j = 0; j < 4; j++) acc[t][u][j] = 0.0f;

    // ldmatrix lane constants
    int rowoff = lane & 15;
    int koff   = (lane >> 4) << 3;     // 0 or 8 (b16 units)
    uint32_t aAddr0 = smem_base + (uint32_t)(((wr * 32 + rowoff) * KPAD2 + koff) * 2);
    uint32_t bAddr0 = smem_base + B_OFF + (uint32_t)(((wc * 48 + rowoff) * KPAD2 + koff) * 2);

    int nc = K >> 5;
    for (int ch = 0; ch < nc; ch++) {
        if (ch + 1 < nc) {
            int k1 = (ch + 1) << 5;
#pragma unroll
            for (int i = 0; i < 4; i++)
                ra[i] = *(const float4*)(Aptr + (size_t)(i << 5) * K + k1);
#pragma unroll
            for (int i = 0; i < 3; i++)
                rb[i] = *(const float4*)(Bptr + (size_t)(i << 5) * K + k1);
        }
        uint32_t aBuf = aAddr0 + (ch & 1) * A_BYTES;
        uint32_t bBuf = bAddr0 + (ch & 1) * B_BYTES;
#pragma unroll
        for (int ks = 0; ks < 2; ks++) {
            uint32_t a[2][4];
#pragma unroll
            for (int t = 0; t < 2; t++)
                ldsm4(a[t][0], a[t][1], a[t][2], a[t][3],
                      aBuf + (uint32_t)((t * 16 * KPAD2 + ks * 16) * 2));
            uint32_t bq[6][2];
#pragma unroll
            for (int p = 0; p < 3; p++) {
                uint32_t q0, q1, q2, q3;
                ldsm4(q0, q1, q2, q3,
                      bBuf + (uint32_t)((p * 16 * KPAD2 + ks * 16) * 2));
                bq[2 * p][0] = q0; bq[2 * p + 1][0] = q1;
                bq[2 * p][1] = q2; bq[2 * p + 1][1] = q3;
            }
#pragma unroll
            for (int u = 0; u < 6; u++) {
                mma16(acc[0][u], a[0], bq[u][0], bq[u][1]);
                mma16(acc[1][u], a[1], bq[u][0], bq[u][1]);
            }
        }
        if (ch + 1 < nc) {
            stage((ch + 1) & 1);
            __syncthreads();
        }
    }
    __syncthreads();   // protect epilogue aliasing of the buffers

    // Epilogue: registers -> staged smem [128][97] with bias/scale/GELU
#pragma unroll
    for (int t = 0; t < 2; t++) {
#pragma unroll
        for (int u = 0; u < 6; u++) {
            int r0 = wr * 32 + t * 16 + g;
            int nn = wc * 48 + u * 8 + 2 * c;
            float b0 = __ldg(bias + n0 + nn);
            float b1 = __ldg(bias + n0 + nn + 1);
            float v0 = acc[t][u][0] + b0, v1 = acc[t][u][1] + b1;
            float v2 = acc[t][u][2] + b0, v3 = acc[t][u][3] + b1;
            if (MODE == 0 && n0 == 0) {
                v0 *= 0.17677669529663689f; v1 *= 0.17677669529663689f;
                v2 *= 0.17677669529663689f; v3 *= 0.17677669529663689f;
            }
            if (MODE == 2) {
                v0 = 0.5f * v0 * (1.0f + erff(v0 * 0.70710678118654752f));
                v1 = 0.5f * v1 * (1.0f + erff(v1 * 0.70710678118654752f));
                v2 = 0.5f * v2 * (1.0f + erff(v2 * 0.70710678118654752f));
                v3 = 0.5f * v3 * (1.0f + erff(v3 * 0.70710678118654752f));
            }
            Sf[r0 * 97 + nn] = v0;       Sf[r0 * 97 + nn + 1] = v1;
            Sf[(r0 + 8) * 97 + nn] = v2; Sf[(r0 + 8) * 97 + nn + 1] = v3;
        }
    }
    __syncthreads();

#pragma unroll
    for (int i = 0; i < 12; i++) {
        int idx = tid + (i << 8);
        int row = idx / 24, q4 = idx - row * 24;
        int m = m0 + row, n = n0 + (q4 << 2);
        float* sp = Sf + row * 97 + (q4 << 2);
        float4 v; v.x = sp[0]; v.y = sp[1]; v.z = sp[2]; v.w = sp[3];
        if (MODE == 0) {
            *(float4*)(g_QKV + (size_t)m * 288 + n) = v;
        } else if (MODE == 1) {
            int d0 = g_DST[m];
            float4 r = *(const float4*)(res + (size_t)d0 * 96 + n);
            v.x += r.x; v.y += r.y; v.z += r.z; v.w += r.w;
            *(float4*)(g_X + (size_t)d0 * 96 + n) = v;
            sp[0] = v.x; sp[1] = v.y; sp[2] = v.z; sp[3] = v.w;
        } else if (MODE == 2) {
            *(float4*)(g_FF + (size_t)m * 384 + n) = v;
        } else {
            float4 r = *(const float4*)(g_X + (size_t)m * 96 + n);
            v.x += r.x; v.y += r.y; v.z += r.z; v.w += r.w;
            *(float4*)(outp + (size_t)m * 96 + n) = v;
        }
    }

    if (MODE == 1) {
        __syncthreads();
        int row = tid >> 1, half = tid & 1;
        const float* rp = Sf + row * 97 + half * 48;
        float s = 0.f, ss = 0.f;
#pragma unroll
        for (int j = 0; j < 48; j++) {
            float v = rp[j];
            s += v; ss = fmaf(v, v, ss);
        }
        s  += __shfl_xor_sync(0xffffffffu, s, 1);
        ss += __shfl_xor_sync(0xffffffffu, ss, 1);
        float mean = s * (1.0f / 96.0f);
        float var  = ss * (1.0f / 96.0f) - mean * mean;
        float inv  = rsqrtf(var + 1e-5f);
        int d0 = g_DST[m0 + row];
        float* op = g_X2 + (size_t)d0 * 96 + half * 48;
#pragma unroll
        for (int j4 = 0; j4 < 12; j4++) {
            int n = half * 48 + j4 * 4;
            float4 o;
            o.x = (rp[j4 * 4]     - mean) * inv * __ldg(g2 + n)     + __ldg(b2 + n);
            o.y = (rp[j4 * 4 + 1] - mean) * inv * __ldg(g2 + n + 1) + __ldg(b2 + n + 1);
            o.z = (rp[j4 * 4 + 2] - mean) * inv * __ldg(g2 + n + 2) + __ldg(b2 + n + 2);
            o.w = (rp[j4 * 4 + 3] - mean) * inv * __ldg(g2 + n + 3) + __ldg(b2 + n + 3);
            *(float4*)(op + j4 * 4) = o;
        }
    }
}

// ---------------------------------------------------------------------------
// MMA attention (tf32): block = (window, head), 352 threads = 11 warps,
// warp owns 32 query rows. Flash over key chunks of 32. Bias from g_SB.
// ---------------------------------------------------------------------------
#define NPAD 352
#define ASTRIDE 36
#define ATTN_SMEM (2 * NPAD * ASTRIDE * 4)   // K + V = 101376 B

__global__ void __launch_bounds__(352, 1) attn_mma(const float* __restrict__ rpb)
{
    extern __shared__ __align__(16) char smraw[];
    uint32_t* Ks = (uint32_t*)smraw;
    uint32_t* Vs = Ks + NPAD * ASTRIDE;

    int w   = blockIdx.x / 3;
    int h   = blockIdx.x - w * 3;
    int tid = threadIdx.x;
    const float* base = g_QKV + (size_t)w * NTOK * 288;

    for (int i = tid; i < NTOK * 32; i += 352) {
        int n = i >> 5, j = i & 31;
        const float* bp = base + n * 288 + h * 32 + j;
        Ks[n * ASTRIDE + j] = __float_as_uint(bp[96]);
        Vs[n * ASTRIDE + j] = __float_as_uint(bp[192]);
    }
    for (int i = NTOK * 32 + tid; i < NPAD * 32; i += 352) {
        int n = i >> 5, j = i & 31;
        Ks[n * ASTRIDE + j] = 0;
        Vs[n * ASTRIDE + j] = 0;
    }
    __syncthreads();

    int wid  = tid >> 5, lane = tid & 31;
    int g    = lane >> 2, c = lane & 3;
    int q0   = wid * 32;

    int iH = w >> 5, iW = (w >> 2) & 7, iD = w & 3;
    int cls = ((iH == 7) << 2) | ((iW == 7) << 1) | (iD == 3);
    const float* SB = g_SB + (size_t)(cls * 3 + h) * NTOK * SBROW;

    uint32_t qa[2][4][4];
    const float* sbp[4];
#pragma unroll
    for (int t = 0; t < 2; t++) {
#pragma unroll
        for (int rr = 0; rr < 2; rr++) {
            int row = q0 + t * 16 + rr * 8 + g;
            int rc  = (row < NTOK) ? row : NTOK - 1;
            sbp[t * 2 + rr] = SB + (size_t)rc * SBROW;
            const float* qp = base + rc * 288 + h * 32;
#pragma unroll
            for (int kk = 0; kk < 4; kk++) {
                qa[t][kk][rr]     = __float_as_uint(qp[kk * 8 + c]);
                qa[t][kk][rr + 2] = __float_as_uint(qp[kk * 8 + c + 4]);
            }
        }
    }

    float mrun[4] = {-1e30f, -1e30f, -1e30f, -1e30f};
    float lrun[4] = {0.f, 0.f, 0.f, 0.f};
    float o[2][4][4];
#pragma unroll
    for (int t = 0; t < 2; t++)
#pragma unroll
        for (int nb = 0; nb < 4; nb++)
#pragma unroll
            for (int j = 0; j < 4; j++) o[t][nb][j] = 0.f;

    for (int kc = 0; kc < NPAD; kc += 32) {
        float sa[2][4][4];
#pragma unroll
        for (int t = 0; t < 2; t++)
#pragma unroll
            for (int nb = 0; nb < 4; nb++)
#pragma unroll
                for (int j = 0; j < 4; j++) sa[t][nb][j] = 0.f;

#pragma unroll
        for (int nb = 0; nb < 4; nb++) {
            int krow = kc + nb * 8 + g;
#pragma unroll
            for (int kk = 0; kk < 4; kk++) {
                uint32_t b0 = Ks[krow * ASTRIDE + kk * 8 + c];
                uint32_t b1 = Ks[krow * ASTRIDE + kk * 8 + c + 4];
                mma8(sa[0][nb], qa[0][kk], b0, b1);
                mma8(sa[1][nb], qa[1][kk], b0, b1);
            }
        }

#pragma unroll
        for (int t = 0; t < 2; t++) {
#pragma unroll
            for (int nb = 0; nb < 4; nb++) {
                int coff = kc + nb * 8 + 2 * c;
                float2 bv0 = *(const float2*)(sbp[t * 2]     + coff);
                float2 bv1 = *(const float2*)(sbp[t * 2 + 1] + coff);
                sa[t][nb][0] += bv0.x; sa[t][nb][1] += bv0.y;
                sa[t][nb][2] += bv1.x; sa[t][nb][3] += bv1.y;
            }
        }

#pragma unroll
        for (int ri = 0; ri < 4; ri++) {
            int t = ri >> 1, rr = ri & 1;
            float mx = -3e4f;
#pragma unroll
            for (int nb = 0; nb < 4; nb++)
                mx = fmaxf(mx, fmaxf(sa[t][nb][rr * 2], sa[t][nb][rr * 2 + 1]));
            mx = fmaxf(mx, __shfl_xor_sync(0xffffffffu, mx, 1));
            mx = fmaxf(mx, __shfl_xor_sync(0xffffffffu, mx, 2));
            float mnew = fmaxf(mrun[ri], mx);
            float corr = __expf(mrun[ri] - mnew);
            mrun[ri] = mnew;
            float ls = 0.f;
#pragma unroll
            for (int nb = 0; nb < 4; nb++) {
                float p0 = __expf(sa[t][nb][rr * 2]     - mnew);
                float p1 = __expf(sa[t][nb][rr * 2 + 1] - mnew);
                sa[t][nb][rr * 2]     = p0;
                sa[t][nb][rr * 2 + 1] = p1;
                ls += p0 + p1;
            }
            ls += __shfl_xor_sync(0xffffffffu, ls, 1);
            ls += __shfl_xor_sync(0xffffffffu, ls, 2);
            lrun[ri] = lrun[ri] * corr + ls;
#pragma unroll
            for (int nb = 0; nb < 4; nb++) {
                o[t][nb][rr * 2]     *= corr;
                o[t][nb][rr * 2 + 1] *= corr;
            }
        }

        int src0 = (lane & ~3) | (c >> 1);
        int src1 = src0 + 2;
        int par  = c & 1;
#pragma unroll
        for (int kb = 0; kb < 4; kb++) {
            uint32_t ua[2][4];
#pragma unroll
            for (int t = 0; t < 2; t++) {
                float v00 = __shfl_sync(0xffffffffu, sa[t][kb][0], src0);
                float v01 = __shfl_sync(0xffffffffu, sa[t][kb][1], src0);
                float v10 = __shfl_sync(0xffffffffu, sa[t][kb][2], src0);
                float v11 = __shfl_sync(0xffffffffu, sa[t][kb][3], src0);
                float w00 = __shfl_sync(0xffffffffu, sa[t][kb][0], src1);
                float w01 = __shfl_sync(0xffffffffu, sa[t][kb][1], src1);
                float w10 = __shfl_sync(0xffffffffu, sa[t][kb][2], src1);
                float w11 = __shfl_sync(0xffffffffu, sa[t][kb][3], src1);
                ua[t][0] = __float_as_uint(par ? v01 : v00);
                ua[t][1] = __float_as_uint(par ? v11 : v10);
                ua[t][2] = __float_as_uint(par ? w01 : w00);
                ua[t][3] = __float_as_uint(par ? w11 : w10);
            }
            int vr0 = kc + kb * 8 + c;
#pragma unroll
            for (int nb = 0; nb < 4; nb++) {
                uint32_t b0 = Vs[vr0 * ASTRIDE + nb * 8 + g];
                uint32_t b1 = Vs[(vr0 + 4) * ASTRIDE + nb * 8 + g];
                mma8(o[0][nb], ua[0], b0, b1);
                mma8(o[1][nb], ua[1], b0, b1);
            }
        }
    }

    float inv[4];
#pragma unroll
    for (int ri = 0; ri < 4; ri++) inv[ri] = 1.0f / lrun[ri];

#pragma unroll
    for (int t = 0; t < 2; t++) {
        int r0 = q0 + t * 16 + g;
#pragma unroll
        for (int rr = 0; rr < 2; rr++) {
            int row = r0 + rr * 8;
            if (row < NTOK) {
                int ri = t * 2 + rr;
                float* op = g_O + ((size_t)w * NTOK + row) * CDIM + h * 32;
#pragma unroll
                for (int nb = 0; nb < 4; nb++) {
                    float2 st;
                    st.x = o[t][nb][rr * 2]     * inv[ri];
                    st.y = o[t][nb][rr * 2 + 1] * inv[ri];
                    *(float2*)(op + nb * 8 + 2 * c) = st;
                }
            }
        }
    }
}

// ---------------------------------------------------------------------------
// Launch
// ---------------------------------------------------------------------------
extern "C" void kernel_launch(void* const* d_in, const int* in_sizes, int n_in,
                              void* d_out, int out_size)
{
    const float* x      = (const float*)d_in[0];
    const float* n1g    = (const float*)d_in[1];
    const float* n1b    = (const float*)d_in[2];
    const float* qkv_w  = (const float*)d_in[3];
    const float* qkv_b  = (const float*)d_in[4];
    const float* rpb    = (const float*)d_in[5];
    const float* proj_w = (const float*)d_in[6];
    const float* proj_b = (const float*)d_in[7];
    const float* n2g    = (const float*)d_in[8];
    const float* n2b    = (const float*)d_in[9];
    const float* fc1_w  = (const float*)d_in[10];
    const float* fc1_b  = (const float*)d_in[11];
    const float* fc2_w  = (const float*)d_in[12];
    const float* fc2_b  = (const float*)d_in[13];
    float* out = (float*)d_out;

    cudaFuncSetAttribute(gemm_mma<0>, cudaFuncAttributeMaxDynamicSharedMemorySize, GEMM_SMEM);
    cudaFuncSetAttribute(gemm_mma<1>, cudaFuncAttributeMaxDynamicSharedMemorySize, GEMM_SMEM);
    cudaFuncSetAttribute(gemm_mma<2>, cudaFuncAttributeMaxDynamicSharedMemorySize, GEMM_SMEM);
    cudaFuncSetAttribute(gemm_mma<3>, cudaFuncAttributeMaxDynamicSharedMemorySize, GEMM_SMEM);
    cudaFuncSetAttribute(attn_mma, cudaFuncAttributeMaxDynamicSharedMemorySize, ATTN_SMEM);

    transpose_all<<<432, 256>>>(qkv_w, proj_w, fc1_w, fc2_w);
    bias_precompute<<<(24 * NTOK * SBROW + 255) / 256, 256>>>(rpb);

    ln_kernel<<<LTOK / 8, 256>>>(x, n1g, n1b);

    gemm_mma<0><<<dim3(3, 686), 256, GEMM_SMEM>>>(qkv_b, nullptr, nullptr, 96, nullptr, nullptr);

    attn_mma<<<NWIN * NHEAD, 352, ATTN_SMEM>>>(rpb);

    gemm_mma<1><<<dim3(1, 686), 256, GEMM_SMEM>>>(proj_b, x, nullptr, 96, n2g, n2b);

    gemm_mma<2><<<dim3(4, 686), 256, GEMM_SMEM>>>(fc1_b, nullptr, nullptr, 96, nullptr, nullptr);

    gemm_mma<3><<<dim3(1, 686), 256, GEMM_SMEM>>>(fc2_b, nullptr, out, 384, nullptr, nullptr);
}

// round 9
// speedup vs baseline: 1.2176x; 1.1311x over previous
#include <cuda_runtime.h>
#include <cuda_bf16.h>
#include <cstdint>

// ---------------------------------------------------------------------------
// Problem constants
// ---------------------------------------------------------------------------
#define HH   56
#define WWID 56
#define DDEP 28
#define LTOK 87808          // 56*56*28
#define CDIM 96
#define NWIN 256
#define NTOK 343
#define NHEAD 3
#define FF   384
#define BN   96             // GEMM N tile
#define BM   128            // GEMM M tile

// ---------------------------------------------------------------------------
// Scratch (device globals; no allocation allowed)
// ---------------------------------------------------------------------------
__device__ __align__(16) float g_QKV[(size_t)LTOK * 288];
__device__ __align__(16) float g_X  [(size_t)LTOK * CDIM];
__device__ int g_DST[LTOK];
// bf16 activations
__device__ __align__(16) __nv_bfloat16 g_Hb [(size_t)LTOK * CDIM];
__device__ __align__(16) __nv_bfloat16 g_Ob [(size_t)LTOK * CDIM];
__device__ __align__(16) __nv_bfloat16 g_X2b[(size_t)LTOK * CDIM];
__device__ __align__(16) __nv_bfloat16 g_FFb[(size_t)LTOK * FF];
// bf16 pre-transposed weights [N,K]
__device__ __align__(16) __nv_bfloat16 g_WtQKVh [288 * 96];
__device__ __align__(16) __nv_bfloat16 g_WtPROJh[96 * 96];
__device__ __align__(16) __nv_bfloat16 g_WtFC1h [384 * 96];
__device__ __align__(16) __nv_bfloat16 g_WtFC2h [96 * 384];
// precomputed bias+mask table: [8 classes][3 heads][343 rows][352 cols]
#define SBROW 352
__device__ __align__(16) float g_SB[24 * NTOK * SBROW];

// ---------------------------------------------------------------------------
// helpers
// ---------------------------------------------------------------------------
__device__ __forceinline__ void mma8(float* c, const uint32_t* a, uint32_t b0, uint32_t b1) {
    asm("mma.sync.aligned.m16n8k8.row.col.f32.tf32.tf32.f32 "
        "{%0,%1,%2,%3}, {%4,%5,%6,%7}, {%8,%9}, {%0,%1,%2,%3};"
        : "+f"(c[0]), "+f"(c[1]), "+f"(c[2]), "+f"(c[3])
        : "r"(a[0]), "r"(a[1]), "r"(a[2]), "r"(a[3]), "r"(b0), "r"(b1));
}
__device__ __forceinline__ void mma16(float* c, const uint32_t* a, uint32_t b0, uint32_t b1) {
    asm("mma.sync.aligned.m16n8k16.row.col.f32.bf16.bf16.f32 "
        "{%0,%1,%2,%3}, {%4,%5,%6,%7}, {%8,%9}, {%0,%1,%2,%3};"
        : "+f"(c[0]), "+f"(c[1]), "+f"(c[2]), "+f"(c[3])
        : "r"(a[0]), "r"(a[1]), "r"(a[2]), "r"(a[3]), "r"(b0), "r"(b1));
}
__device__ __forceinline__ void ldsm4(uint32_t& r0, uint32_t& r1, uint32_t& r2, uint32_t& r3,
                                      uint32_t addr) {
    asm volatile("ldmatrix.sync.aligned.m8n8.x4.shared.b16 {%0,%1,%2,%3}, [%4];"
        : "=r"(r0), "=r"(r1), "=r"(r2), "=r"(r3) : "r"(addr));
}
__device__ __forceinline__ uint32_t bf2(float lo, float hi) {
    uint32_t d;
    asm("cvt.rn.bf16x2.f32 %0, %1, %2;" : "=r"(d) : "f"(hi), "f"(lo));
    return d;
}
__device__ __forceinline__ void cp16(uint32_t dst, const void* src) {
    asm volatile("cp.async.cg.shared.global [%0], [%1], 16;" :: "r"(dst), "l"(src));
}

// ---------------------------------------------------------------------------
// Bias+mask table precompute: SB[cls][h][n][m]
// ---------------------------------------------------------------------------
__global__ void bias_precompute(const float* __restrict__ rpb)
{
    int gid = blockIdx.x * 256 + threadIdx.x;
    if (gid >= 24 * NTOK * SBROW) return;
    int m  = gid % SBROW;
    int t  = gid / SBROW;
    int n  = t % NTOK;
    int ch = t / NTOK;
    int h  = ch % 3, cls = ch / 3;
    float v;
    if (m >= NTOK) {
        v = -30000.0f;
    } else {
        int an = n / 49, rn = n - an * 49, bn = rn / 7, cn = rn - bn * 7;
        int am = m / 49, rm = m - am * 49, bm = rm / 7, cm = rm - bm * 7;
        int sub_n = an * 169 + bn * 13 + cn;
        int sub_m = am * 169 + bm * 13 + cm;
        v = rpb[(1098 + sub_n - sub_m) * 3 + h];
        int bh = (cls >> 2) & 1, bw = (cls >> 1) & 1, bd = cls & 1;
        int rgn_n = ((bh ? (an < 4 ? 1 : 2) : 0) * 3 + (bw ? (bn < 4 ? 1 : 2) : 0)) * 3
                  + (bd ? (cn < 4 ? 1 : 2) : 0);
        int rgn_m = ((bh ? (am < 4 ? 1 : 2) : 0) * 3 + (bw ? (bm < 4 ? 1 : 2) : 0)) * 3
                  + (bd ? (cm < 4 ? 1 : 2) : 0);
        if (rgn_n != rgn_m) v -= 100.0f;
    }
    g_SB[gid] = v;
}

// ---------------------------------------------------------------------------
// LayerNorm #1 (one warp per token): gather + shift + partition -> bf16
// ---------------------------------------------------------------------------
__global__ void __launch_bounds__(256) ln_kernel(const float* __restrict__ in,
                                                 const float* __restrict__ gamma,
                                                 const float* __restrict__ beta)
{
    int gw   = (blockIdx.x * 256 + threadIdx.x) >> 5;
    int lane = threadIdx.x & 31;
    if (gw >= LTOK) return;

    int w = gw / NTOK, n = gw - w * NTOK;
    int iH = w >> 5, iW = (w >> 2) & 7, iD = w & 3;
    int a = n / 49; int r = n - a * 49; int b = r / 7; int c = r - b * 7;
    int th = iH * 7 + a + 3; if (th >= HH)   th -= HH;
    int tw = iW * 7 + b + 3; if (tw >= WWID) tw -= WWID;
    int td = iD * 7 + c + 3; if (td >= DDEP) td -= DDEP;
    int src = (th * WWID + tw) * DDEP + td;
    if (lane == 0) g_DST[gw] = src;
    const float* inp = in + (size_t)src * CDIM;
    __nv_bfloat16* outp = g_Hb + (size_t)gw * CDIM;

    float v0 = inp[lane], v1 = inp[lane + 32], v2 = inp[lane + 64];
    float s  = v0 + v1 + v2;
    float ss = fmaf(v0, v0, fmaf(v1, v1, v2 * v2));
#pragma unroll
    for (int o = 16; o; o >>= 1) {
        s  += __shfl_xor_sync(0xffffffffu, s, o);
        ss += __shfl_xor_sync(0xffffffffu, ss, o);
    }
    float mean = s * (1.0f / 96.0f);
    float var  = ss * (1.0f / 96.0f) - mean * mean;
    float inv  = rsqrtf(var + 1e-5f);
    outp[lane]      = __float2bfloat16((v0 - mean) * inv * gamma[lane]      + beta[lane]);
    outp[lane + 32] = __float2bfloat16((v1 - mean) * inv * gamma[lane + 32] + beta[lane + 32]);
    outp[lane + 64] = __float2bfloat16((v2 - mean) * inv * gamma[lane + 64] + beta[lane + 64]);
}

// ---------------------------------------------------------------------------
// All weight transposes in one launch: W[K,N] -> bf16 Wt[N,K]
// ---------------------------------------------------------------------------
__global__ void transpose_all(const float* __restrict__ qkv_w,
                              const float* __restrict__ proj_w,
                              const float* __restrict__ fc1_w,
                              const float* __restrict__ fc2_w)
{
    int idx = blockIdx.x * 256 + threadIdx.x;
    if (idx < 27648) {
        int k = idx / 288, n = idx - k * 288;
        g_WtQKVh[n * 96 + k] = __float2bfloat16(qkv_w[idx]);
    } else if (idx < 36864) {
        int j = idx - 27648;
        int k = j / 96, n = j - k * 96;
        g_WtPROJh[n * 96 + k] = __float2bfloat16(proj_w[j]);
    } else if (idx < 73728) {
        int j = idx - 36864;
        int k = j / 384, n = j - k * 384;
        g_WtFC1h[n * 96 + k] = __float2bfloat16(fc1_w[j]);
    } else if (idx < 110592) {
        int j = idx - 73728;
        int k = j / 96, n = j - k * 96;
        g_WtFC2h[n * 384 + k] = __float2bfloat16(fc2_w[j]);
    }
}

// ---------------------------------------------------------------------------
// cp.async bf16 mma GEMM: C[128,96] = A[128,K] @ Wt[96,K]^T
// KC=96 chunks; K=96 -> single stage, K=384 -> double-buffered pipeline.
// MODE 0: qkv (q-scale)  MODE 1: proj (scatter+residual + fused LN2->bf16)
// MODE 2: fc1 (GELU->bf16)  MODE 3: fc2 (+residual -> d_out)
// ---------------------------------------------------------------------------
#define KPAD2 104                       // b16 units; 208B row stride, LDSM-clean
#define A_STG (128 * KPAD2 * 2)         // 26624 B
#define B_STG (96 * KPAD2 * 2)          // 19968 B
#define STAGE_BYTES (A_STG + B_STG)     // 46592 B
#define GEMM_SMEM_1 49664               // single-stage modes (epilogue dominates)
#define GEMM_SMEM_2 (2 * STAGE_BYTES)   // fc2: 93184 B

template <int MODE>
__global__ void __launch_bounds__(256) gemm_mma(const float* __restrict__ bias,
                                                const float* __restrict__ res,
                                                float* __restrict__ outp,
                                                int Kb,
                                                const float* __restrict__ g2,
                                                const float* __restrict__ b2)
{
    extern __shared__ __align__(16) char smraw[];
    float* Sf = (float*)smraw;   // epilogue staging [128][97]

    const __nv_bfloat16* A  = (MODE == 0) ? g_Hb : (MODE == 1) ? g_Ob
                            : (MODE == 2) ? g_X2b : g_FFb;
    const __nv_bfloat16* Wt = (MODE == 0) ? g_WtQKVh : (MODE == 1) ? g_WtPROJh
                            : (MODE == 2) ? g_WtFC1h : g_WtFC2h;

    int tid  = threadIdx.x;
    int wid  = tid >> 5, lane = tid & 31;
    int wr   = wid >> 1, wc = wid & 1;
    int g    = lane >> 2, c = lane & 3;
    int m0   = blockIdx.y * BM;
    int n0   = blockIdx.x * BN;

    uint32_t smem_base = (uint32_t)__cvta_generic_to_shared(smraw);

    const __nv_bfloat16* Agm = A  + (size_t)m0 * Kb;
    const __nv_bfloat16* Bgm = Wt + (size_t)n0 * Kb;

    // stage one 96-wide K chunk into buffer `buf` via cp.async (16B ops)
    auto stage = [&](int chunk, int buf) {
        uint32_t dstA = smem_base + buf * STAGE_BYTES;
        uint32_t dstB = dstA + A_STG;
        const __nv_bfloat16* As = Agm + chunk * 96;
        const __nv_bfloat16* Bs = Bgm + chunk * 96;
#pragma unroll
        for (int i = 0; i < 6; i++) {               // A: 1536 16B ops
            int idx = tid + (i << 8);
            int row = idx / 12, c16 = idx - row * 12;
            cp16(dstA + (uint32_t)((row * KPAD2 + c16 * 8) * 2),
                 As + (size_t)row * Kb + c16 * 8);
        }
#pragma unroll
        for (int i = 0; i < 5; i++) {               // B: 1152 16B ops
            int idx = tid + (i << 8);
            if (idx < 1152) {
                int row = idx / 12, c16 = idx - row * 12;
                cp16(dstB + (uint32_t)((row * KPAD2 + c16 * 8) * 2),
                     Bs + (size_t)row * Kb + c16 * 8);
            }
        }
        asm volatile("cp.async.commit_group;" ::: "memory");
    };

    int nc = Kb / 96;
    stage(0, 0);
    if (nc > 1) stage(1, 1);
    if (nc > 1) asm volatile("cp.async.wait_group 1;" ::: "memory");
    else        asm volatile("cp.async.wait_group 0;" ::: "memory");
    __syncthreads();

    float acc[2][6][4];
#pragma unroll
    for (int t = 0; t < 2; t++)
#pragma unroll
        for (int u = 0; u < 6; u++)
#pragma unroll
            for (int j = 0; j < 4; j++) acc[t][u][j] = 0.0f;

    // ldmatrix lane constants
    int rowoff = lane & 15;
    int koff   = (lane >> 4) << 3;     // 0 or 8 b16
    uint32_t aAddr0 = smem_base + (uint32_t)(((wr * 32 + rowoff) * KPAD2 + koff) * 2);
    uint32_t bAddr0 = smem_base + A_STG + (uint32_t)(((wc * 48 + rowoff) * KPAD2 + koff) * 2);

    for (int chv = 0; chv < nc; chv++) {
        uint32_t aBuf = aAddr0 + (chv & 1) * STAGE_BYTES;
        uint32_t bBuf = bAddr0 + (chv & 1) * STAGE_BYTES;
#pragma unroll
        for (int ks = 0; ks < 6; ks++) {
            uint32_t a[2][4];
#pragma unroll
            for (int t = 0; t < 2; t++)
                ldsm4(a[t][0], a[t][1], a[t][2], a[t][3],
                      aBuf + (uint32_t)((t * 16 * KPAD2 + ks * 16) * 2));
            uint32_t bq[6][2];
#pragma unroll
            for (int p = 0; p < 3; p++) {
                uint32_t q0, q1, q2, q3;
                ldsm4(q0, q1, q2, q3,
                      bBuf + (uint32_t)((p * 16 * KPAD2 + ks * 16) * 2));
                bq[2 * p][0] = q0; bq[2 * p + 1][0] = q1;
                bq[2 * p][1] = q2; bq[2 * p + 1][1] = q3;
            }
#pragma unroll
            for (int u = 0; u < 6; u++) {
                mma16(acc[0][u], a[0], bq[u][0], bq[u][1]);
                mma16(acc[1][u], a[1], bq[u][0], bq[u][1]);
            }
        }
        if (chv + 1 < nc) {
            __syncthreads();                         // done reading buf chv&1
            if (chv + 2 < nc) stage(chv + 2, chv & 1);
            if (chv + 2 < nc) asm volatile("cp.async.wait_group 1;" ::: "memory");
            else              asm volatile("cp.async.wait_group 0;" ::: "memory");
            __syncthreads();
        }
    }
    __syncthreads();   // protect epilogue aliasing of the buffers

    // Epilogue: registers -> staged smem [128][97] with bias/scale/GELU
#pragma unroll
    for (int t = 0; t < 2; t++) {
#pragma unroll
        for (int u = 0; u < 6; u++) {
            int r0 = wr * 32 + t * 16 + g;
            int nn = wc * 48 + u * 8 + 2 * c;
            float b0 = __ldg(bias + n0 + nn);
            float b1 = __ldg(bias + n0 + nn + 1);
            float v0 = acc[t][u][0] + b0, v1 = acc[t][u][1] + b1;
            float v2 = acc[t][u][2] + b0, v3 = acc[t][u][3] + b1;
            if (MODE == 0 && n0 == 0) {
                v0 *= 0.17677669529663689f; v1 *= 0.17677669529663689f;
                v2 *= 0.17677669529663689f; v3 *= 0.17677669529663689f;
            }
            if (MODE == 2) {
                v0 = 0.5f * v0 * (1.0f + erff(v0 * 0.70710678118654752f));
                v1 = 0.5f * v1 * (1.0f + erff(v1 * 0.70710678118654752f));
                v2 = 0.5f * v2 * (1.0f + erff(v2 * 0.70710678118654752f));
                v3 = 0.5f * v3 * (1.0f + erff(v3 * 0.70710678118654752f));
            }
            Sf[r0 * 97 + nn] = v0;       Sf[r0 * 97 + nn + 1] = v1;
            Sf[(r0 + 8) * 97 + nn] = v2; Sf[(r0 + 8) * 97 + nn + 1] = v3;
        }
    }
    __syncthreads();

#pragma unroll
    for (int i = 0; i < 12; i++) {
        int idx = tid + (i << 8);
        int row = idx / 24, q4 = idx - row * 24;
        int m = m0 + row, n = n0 + (q4 << 2);
        float* sp = Sf + row * 97 + (q4 << 2);
        float4 v; v.x = sp[0]; v.y = sp[1]; v.z = sp[2]; v.w = sp[3];
        if (MODE == 0) {
            *(float4*)(g_QKV + (size_t)m * 288 + n) = v;
        } else if (MODE == 1) {
            int d0 = g_DST[m];
            float4 r = *(const float4*)(res + (size_t)d0 * 96 + n);
            v.x += r.x; v.y += r.y; v.z += r.z; v.w += r.w;
            *(float4*)(g_X + (size_t)d0 * 96 + n) = v;
            sp[0] = v.x; sp[1] = v.y; sp[2] = v.z; sp[3] = v.w;
        } else if (MODE == 2) {
            uint2 u;
            u.x = bf2(v.x, v.y); u.y = bf2(v.z, v.w);
            *(uint2*)(g_FFb + (size_t)m * 384 + n) = u;
        } else {
            float4 r = *(const float4*)(g_X + (size_t)m * 96 + n);
            v.x += r.x; v.y += r.y; v.z += r.z; v.w += r.w;
            *(float4*)(outp + (size_t)m * 96 + n) = v;
        }
    }

    if (MODE == 1) {
        __syncthreads();
        int row = tid >> 1, half = tid & 1;
        const float* rp = Sf + row * 97 + half * 48;
        float s = 0.f, ss = 0.f;
#pragma unroll
        for (int j = 0; j < 48; j++) {
            float v = rp[j];
            s += v; ss = fmaf(v, v, ss);
        }
        s  += __shfl_xor_sync(0xffffffffu, s, 1);
        ss += __shfl_xor_sync(0xffffffffu, ss, 1);
        float mean = s * (1.0f / 96.0f);
        float var  = ss * (1.0f / 96.0f) - mean * mean;
        float inv  = rsqrtf(var + 1e-5f);
        int d0 = g_DST[m0 + row];
        __nv_bfloat16* op = g_X2b + (size_t)d0 * 96 + half * 48;
#pragma unroll
        for (int j4 = 0; j4 < 12; j4++) {
            int n = half * 48 + j4 * 4;
            float o0 = (rp[j4 * 4]     - mean) * inv * __ldg(g2 + n)     + __ldg(b2 + n);
            float o1 = (rp[j4 * 4 + 1] - mean) * inv * __ldg(g2 + n + 1) + __ldg(b2 + n + 1);
            float o2 = (rp[j4 * 4 + 2] - mean) * inv * __ldg(g2 + n + 2) + __ldg(b2 + n + 2);
            float o3 = (rp[j4 * 4 + 3] - mean) * inv * __ldg(g2 + n + 3) + __ldg(b2 + n + 3);
            uint2 u; u.x = bf2(o0, o1); u.y = bf2(o2, o3);
            *(uint2*)(op + j4 * 4) = u;
        }
    }
}

// ---------------------------------------------------------------------------
// MMA attention (tf32): block = (window, head), 352 threads = 11 warps,
// warp owns 32 query rows. Flash over key chunks of 32. Bias from g_SB.
// Output stored bf16 (proj consumes bf16).
// ---------------------------------------------------------------------------
#define NPAD 352
#define ASTRIDE 36
#define ATTN_SMEM (2 * NPAD * ASTRIDE * 4)   // K + V = 101376 B

__global__ void __launch_bounds__(352, 1) attn_mma(const float* __restrict__ rpb)
{
    extern __shared__ __align__(16) char smraw[];
    uint32_t* Ks = (uint32_t*)smraw;
    uint32_t* Vs = Ks + NPAD * ASTRIDE;

    int w   = blockIdx.x / 3;
    int h   = blockIdx.x - w * 3;
    int tid = threadIdx.x;
    const float* base = g_QKV + (size_t)w * NTOK * 288;

    for (int i = tid; i < NTOK * 32; i += 352) {
        int n = i >> 5, j = i & 31;
        const float* bp = base + n * 288 + h * 32 + j;
        Ks[n * ASTRIDE + j] = __float_as_uint(bp[96]);
        Vs[n * ASTRIDE + j] = __float_as_uint(bp[192]);
    }
    for (int i = NTOK * 32 + tid; i < NPAD * 32; i += 352) {
        int n = i >> 5, j = i & 31;
        Ks[n * ASTRIDE + j] = 0;
        Vs[n * ASTRIDE + j] = 0;
    }
    __syncthreads();

    int wid  = tid >> 5, lane = tid & 31;
    int g    = lane >> 2, c = lane & 3;
    int q0   = wid * 32;

    int iH = w >> 5, iW = (w >> 2) & 7, iD = w & 3;
    int cls = ((iH == 7) << 2) | ((iW == 7) << 1) | (iD == 3);
    const float* SB = g_SB + (size_t)(cls * 3 + h) * NTOK * SBROW;

    uint32_t qa[2][4][4];
    const float* sbp[4];
#pragma unroll
    for (int t = 0; t < 2; t++) {
#pragma unroll
        for (int rr = 0; rr < 2; rr++) {
            int row = q0 + t * 16 + rr * 8 + g;
            int rc  = (row < NTOK) ? row : NTOK - 1;
            sbp[t * 2 + rr] = SB + (size_t)rc * SBROW;
            const float* qp = base + rc * 288 + h * 32;
#pragma unroll
            for (int kk = 0; kk < 4; kk++) {
                qa[t][kk][rr]     = __float_as_uint(qp[kk * 8 + c]);
                qa[t][kk][rr + 2] = __float_as_uint(qp[kk * 8 + c + 4]);
            }
        }
    }

    float mrun[4] = {-1e30f, -1e30f, -1e30f, -1e30f};
    float lrun[4] = {0.f, 0.f, 0.f, 0.f};
    float o[2][4][4];
#pragma unroll
    for (int t = 0; t < 2; t++)
#pragma unroll
        for (int nb = 0; nb < 4; nb++)
#pragma unroll
            for (int j = 0; j < 4; j++) o[t][nb][j] = 0.f;

    for (int kc = 0; kc < NPAD; kc += 32) {
        float sa[2][4][4];
#pragma unroll
        for (int t = 0; t < 2; t++)
#pragma unroll
            for (int nb = 0; nb < 4; nb++)
#pragma unroll
                for (int j = 0; j < 4; j++) sa[t][nb][j] = 0.f;

#pragma unroll
        for (int nb = 0; nb < 4; nb++) {
            int krow = kc + nb * 8 + g;
#pragma unroll
            for (int kk = 0; kk < 4; kk++) {
                uint32_t b0 = Ks[krow * ASTRIDE + kk * 8 + c];
                uint32_t b1 = Ks[krow * ASTRIDE + kk * 8 + c + 4];
                mma8(sa[0][nb], qa[0][kk], b0, b1);
                mma8(sa[1][nb], qa[1][kk], b0, b1);
            }
        }

#pragma unroll
        for (int t = 0; t < 2; t++) {
#pragma unroll
            for (int nb = 0; nb < 4; nb++) {
                int coff = kc + nb * 8 + 2 * c;
                float2 bv0 = *(const float2*)(sbp[t * 2]     + coff);
                float2 bv1 = *(const float2*)(sbp[t * 2 + 1] + coff);
                sa[t][nb][0] += bv0.x; sa[t][nb][1] += bv0.y;
                sa[t][nb][2] += bv1.x; sa[t][nb][3] += bv1.y;
            }
        }

#pragma unroll
        for (int ri = 0; ri < 4; ri++) {
            int t = ri >> 1, rr = ri & 1;
            float mx = -3e4f;
#pragma unroll
            for (int nb = 0; nb < 4; nb++)
                mx = fmaxf(mx, fmaxf(sa[t][nb][rr * 2], sa[t][nb][rr * 2 + 1]));
            mx = fmaxf(mx, __shfl_xor_sync(0xffffffffu, mx, 1));
            mx = fmaxf(mx, __shfl_xor_sync(0xffffffffu, mx, 2));
            float mnew = fmaxf(mrun[ri], mx);
            float corr = __expf(mrun[ri] - mnew);
            mrun[ri] = mnew;
            float ls = 0.f;
#pragma unroll
            for (int nb = 0; nb < 4; nb++) {
                float p0 = __expf(sa[t][nb][rr * 2]     - mnew);
                float p1 = __expf(sa[t][nb][rr * 2 + 1] - mnew);
                sa[t][nb][rr * 2]     = p0;
                sa[t][nb][rr * 2 + 1] = p1;
                ls += p0 + p1;
            }
            ls += __shfl_xor_sync(0xffffffffu, ls, 1);
            ls += __shfl_xor_sync(0xffffffffu, ls, 2);
            lrun[ri] = lrun[ri] * corr + ls;
#pragma unroll
            for (int nb = 0; nb < 4; nb++) {
                o[t][nb][rr * 2]     *= corr;
                o[t][nb][rr * 2 + 1] *= corr;
            }
        }

        int src0 = (lane & ~3) | (c >> 1);
        int src1 = src0 + 2;
        int par  = c & 1;
#pragma unroll
        for (int kb = 0; kb < 4; kb++) {
            uint32_t ua[2][4];
#pragma unroll
            for (int t = 0; t < 2; t++) {
                float v00 = __shfl_sync(0xffffffffu, sa[t][kb][0], src0);
                float v01 = __shfl_sync(0xffffffffu, sa[t][kb][1], src0);
                float v10 = __shfl_sync(0xffffffffu, sa[t][kb][2], src0);
                float v11 = __shfl_sync(0xffffffffu, sa[t][kb][3], src0);
                float w00 = __shfl_sync(0xffffffffu, sa[t][kb][0], src1);
                float w01 = __shfl_sync(0xffffffffu, sa[t][kb][1], src1);
                float w10 = __shfl_sync(0xffffffffu, sa[t][kb][2], src1);
                float w11 = __shfl_sync(0xffffffffu, sa[t][kb][3], src1);
                ua[t][0] = __float_as_uint(par ? v01 : v00);
                ua[t][1] = __float_as_uint(par ? v11 : v10);
                ua[t][2] = __float_as_uint(par ? w01 : w00);
                ua[t][3] = __float_as_uint(par ? w11 : w10);
            }
            int vr0 = kc + kb * 8 + c;
#pragma unroll
            for (int nb = 0; nb < 4; nb++) {
                uint32_t b0 = Vs[vr0 * ASTRIDE + nb * 8 + g];
                uint32_t b1 = Vs[(vr0 + 4) * ASTRIDE + nb * 8 + g];
                mma8(o[0][nb], ua[0], b0, b1);
                mma8(o[1][nb], ua[1], b0, b1);
            }
        }
    }

    float inv[4];
#pragma unroll
    for (int ri = 0; ri < 4; ri++) inv[ri] = 1.0f / lrun[ri];

#pragma unroll
    for (int t = 0; t < 2; t++) {
        int r0 = q0 + t * 16 + g;
#pragma unroll
        for (int rr = 0; rr < 2; rr++) {
            int row = r0 + rr * 8;
            if (row < NTOK) {
                int ri = t * 2 + rr;
                __nv_bfloat16* op = g_Ob + ((size_t)w * NTOK + row) * CDIM + h * 32;
#pragma unroll
                for (int nb = 0; nb < 4; nb++) {
                    uint32_t p = bf2(o[t][nb][rr * 2] * inv[ri],
                                     o[t][nb][rr * 2 + 1] * inv[ri]);
                    *(uint32_t*)(op + nb * 8 + 2 * c) = p;
                }
            }
        }
    }
}

// ---------------------------------------------------------------------------
// Launch
// ---------------------------------------------------------------------------
extern "C" void kernel_launch(void* const* d_in, const int* in_sizes, int n_in,
                              void* d_out, int out_size)
{
    const float* x      = (const float*)d_in[0];
    const float* n1g    = (const float*)d_in[1];
    const float* n1b    = (const float*)d_in[2];
    const float* qkv_w  = (const float*)d_in[3];
    const float* qkv_b  = (const float*)d_in[4];
    const float* rpb    = (const float*)d_in[5];
    const float* proj_w = (const float*)d_in[6];
    const float* proj_b = (const float*)d_in[7];
    const float* n2g    = (const float*)d_in[8];
    const float* n2b    = (const float*)d_in[9];
    const float* fc1_w  = (const float*)d_in[10];
    const float* fc1_b  = (const float*)d_in[11];
    const float* fc2_w  = (const float*)d_in[12];
    const float* fc2_b  = (const float*)d_in[13];
    float* out = (float*)d_out;

    cudaFuncSetAttribute(gemm_mma<0>, cudaFuncAttributeMaxDynamicSharedMemorySize, GEMM_SMEM_1);
    cudaFuncSetAttribute(gemm_mma<1>, cudaFuncAttributeMaxDynamicSharedMemorySize, GEMM_SMEM_1);
    cudaFuncSetAttribute(gemm_mma<2>, cudaFuncAttributeMaxDynamicSharedMemorySize, GEMM_SMEM_1);
    cudaFuncSetAttribute(gemm_mma<3>, cudaFuncAttributeMaxDynamicSharedMemorySize, GEMM_SMEM_2);
    cudaFuncSetAttribute(attn_mma, cudaFuncAttributeMaxDynamicSharedMemorySize, ATTN_SMEM);

    transpose_all<<<432, 256>>>(qkv_w, proj_w, fc1_w, fc2_w);
    bias_precompute<<<(24 * NTOK * SBROW + 255) / 256, 256>>>(rpb);

    ln_kernel<<<LTOK / 8, 256>>>(x, n1g, n1b);

    gemm_mma<0><<<dim3(3, 686), 256, GEMM_SMEM_1>>>(qkv_b, nullptr, nullptr, 96, nullptr, nullptr);

    attn_mma<<<NWIN * NHEAD, 352, ATTN_SMEM>>>(rpb);

    gemm_mma<1><<<dim3(1, 686), 256, GEMM_SMEM_1>>>(proj_b, x, nullptr, 96, n2g, n2b);

    gemm_mma<2><<<dim3(4, 686), 256, GEMM_SMEM_1>>>(fc1_b, nullptr, nullptr, 96, nullptr, nullptr);

    gemm_mma<3><<<dim3(1, 686), 256, GEMM_SMEM_2>>>(fc2_b, nullptr, out, 384, nullptr, nullptr);
}

// round 10
// speedup vs baseline: 1.3350x; 1.0964x over previous
#include <cuda_runtime.h>
#include <cuda_bf16.h>
#include <cstdint>

// ---------------------------------------------------------------------------
// Problem constants
// ---------------------------------------------------------------------------
#define HH   56
#define WWID 56
#define DDEP 28
#define LTOK 87808          // 56*56*28
#define CDIM 96
#define NWIN 256
#define NTOK 343
#define NHEAD 3
#define FF   384
#define BN   96             // GEMM N tile
#define BM   128            // GEMM M tile

// ---------------------------------------------------------------------------
// Scratch (device globals; no allocation allowed)
// ---------------------------------------------------------------------------
__device__ __align__(16) float g_QKV[(size_t)LTOK * 288];
__device__ __align__(16) float g_X  [(size_t)LTOK * CDIM];
__device__ int g_DST[LTOK];
// bf16 activations
__device__ __align__(16) __nv_bfloat16 g_Hb [(size_t)LTOK * CDIM];
__device__ __align__(16) __nv_bfloat16 g_Ob [(size_t)LTOK * CDIM];
__device__ __align__(16) __nv_bfloat16 g_X2b[(size_t)LTOK * CDIM];
__device__ __align__(16) __nv_bfloat16 g_FFb[(size_t)LTOK * FF];
// bf16 pre-transposed weights [N,K]
__device__ __align__(16) __nv_bfloat16 g_WtQKVh [288 * 96];
__device__ __align__(16) __nv_bfloat16 g_WtPROJh[96 * 96];
__device__ __align__(16) __nv_bfloat16 g_WtFC1h [384 * 96];
__device__ __align__(16) __nv_bfloat16 g_WtFC2h [96 * 384];
// precomputed bias+mask table: [8 classes][3 heads][343 rows][352 cols]
#define SBROW 352
__device__ __align__(16) float g_SB[24 * NTOK * SBROW];

// ---------------------------------------------------------------------------
// helpers
// ---------------------------------------------------------------------------
__device__ __forceinline__ void mma16(float* c, const uint32_t* a, uint32_t b0, uint32_t b1) {
    asm("mma.sync.aligned.m16n8k16.row.col.f32.bf16.bf16.f32 "
        "{%0,%1,%2,%3}, {%4,%5,%6,%7}, {%8,%9}, {%0,%1,%2,%3};"
        : "+f"(c[0]), "+f"(c[1]), "+f"(c[2]), "+f"(c[3])
        : "r"(a[0]), "r"(a[1]), "r"(a[2]), "r"(a[3]), "r"(b0), "r"(b1));
}
__device__ __forceinline__ void ldsm4(uint32_t& r0, uint32_t& r1, uint32_t& r2, uint32_t& r3,
                                      uint32_t addr) {
    asm volatile("ldmatrix.sync.aligned.m8n8.x4.shared.b16 {%0,%1,%2,%3}, [%4];"
        : "=r"(r0), "=r"(r1), "=r"(r2), "=r"(r3) : "r"(addr));
}
__device__ __forceinline__ void ldsm4t(uint32_t& r0, uint32_t& r1, uint32_t& r2, uint32_t& r3,
                                       uint32_t addr) {
    asm volatile("ldmatrix.sync.aligned.m8n8.x4.trans.shared.b16 {%0,%1,%2,%3}, [%4];"
        : "=r"(r0), "=r"(r1), "=r"(r2), "=r"(r3) : "r"(addr));
}
__device__ __forceinline__ uint32_t bf2(float lo, float hi) {
    uint32_t d;
    asm("cvt.rn.bf16x2.f32 %0, %1, %2;" : "=r"(d) : "f"(hi), "f"(lo));
    return d;
}
__device__ __forceinline__ void cp16(uint32_t dst, const void* src) {
    asm volatile("cp.async.cg.shared.global [%0], [%1], 16;" :: "r"(dst), "l"(src));
}

// ---------------------------------------------------------------------------
// Bias+mask table precompute: SB[cls][h][n][m]
// ---------------------------------------------------------------------------
__global__ void bias_precompute(const float* __restrict__ rpb)
{
    int gid = blockIdx.x * 256 + threadIdx.x;
    if (gid >= 24 * NTOK * SBROW) return;
    int m  = gid % SBROW;
    int t  = gid / SBROW;
    int n  = t % NTOK;
    int ch = t / NTOK;
    int h  = ch % 3, cls = ch / 3;
    float v;
    if (m >= NTOK) {
        v = -30000.0f;
    } else {
        int an = n / 49, rn = n - an * 49, bn = rn / 7, cn = rn - bn * 7;
        int am = m / 49, rm = m - am * 49, bm = rm / 7, cm = rm - bm * 7;
        int sub_n = an * 169 + bn * 13 + cn;
        int sub_m = am * 169 + bm * 13 + cm;
        v = rpb[(1098 + sub_n - sub_m) * 3 + h];
        int bh = (cls >> 2) & 1, bw = (cls >> 1) & 1, bd = cls & 1;
        int rgn_n = ((bh ? (an < 4 ? 1 : 2) : 0) * 3 + (bw ? (bn < 4 ? 1 : 2) : 0)) * 3
                  + (bd ? (cn < 4 ? 1 : 2) : 0);
        int rgn_m = ((bh ? (am < 4 ? 1 : 2) : 0) * 3 + (bw ? (bm < 4 ? 1 : 2) : 0)) * 3
                  + (bd ? (cm < 4 ? 1 : 2) : 0);
        if (rgn_n != rgn_m) v -= 100.0f;
    }
    g_SB[gid] = v;
}

// ---------------------------------------------------------------------------
// LayerNorm #1 (one warp per token): gather + shift + partition -> bf16
// ---------------------------------------------------------------------------
__global__ void __launch_bounds__(256) ln_kernel(const float* __restrict__ in,
                                                 const float* __restrict__ gamma,
                                                 const float* __restrict__ beta)
{
    int gw   = (blockIdx.x * 256 + threadIdx.x) >> 5;
    int lane = threadIdx.x & 31;
    if (gw >= LTOK) return;

    int w = gw / NTOK, n = gw - w * NTOK;
    int iH = w >> 5, iW = (w >> 2) & 7, iD = w & 3;
    int a = n / 49; int r = n - a * 49; int b = r / 7; int c = r - b * 7;
    int th = iH * 7 + a + 3; if (th >= HH)   th -= HH;
    int tw = iW * 7 + b + 3; if (tw >= WWID) tw -= WWID;
    int td = iD * 7 + c + 3; if (td >= DDEP) td -= DDEP;
    int src = (th * WWID + tw) * DDEP + td;
    if (lane == 0) g_DST[gw] = src;
    const float* inp = in + (size_t)src * CDIM;
    __nv_bfloat16* outp = g_Hb + (size_t)gw * CDIM;

    float v0 = inp[lane], v1 = inp[lane + 32], v2 = inp[lane + 64];
    float s  = v0 + v1 + v2;
    float ss = fmaf(v0, v0, fmaf(v1, v1, v2 * v2));
#pragma unroll
    for (int o = 16; o; o >>= 1) {
        s  += __shfl_xor_sync(0xffffffffu, s, o);
        ss += __shfl_xor_sync(0xffffffffu, ss, o);
    }
    float mean = s * (1.0f / 96.0f);
    float var  = ss * (1.0f / 96.0f) - mean * mean;
    float inv  = rsqrtf(var + 1e-5f);
    outp[lane]      = __float2bfloat16((v0 - mean) * inv * gamma[lane]      + beta[lane]);
    outp[lane + 32] = __float2bfloat16((v1 - mean) * inv * gamma[lane + 32] + beta[lane + 32]);
    outp[lane + 64] = __float2bfloat16((v2 - mean) * inv * gamma[lane + 64] + beta[lane + 64]);
}

// ---------------------------------------------------------------------------
// All weight transposes in one launch: W[K,N] -> bf16 Wt[N,K]
// ---------------------------------------------------------------------------
__global__ void transpose_all(const float* __restrict__ qkv_w,
                              const float* __restrict__ proj_w,
                              const float* __restrict__ fc1_w,
                              const float* __restrict__ fc2_w)
{
    int idx = blockIdx.x * 256 + threadIdx.x;
    if (idx < 27648) {
        int k = idx / 288, n = idx - k * 288;
        g_WtQKVh[n * 96 + k] = __float2bfloat16(qkv_w[idx]);
    } else if (idx < 36864) {
        int j = idx - 27648;
        int k = j / 96, n = j - k * 96;
        g_WtPROJh[n * 96 + k] = __float2bfloat16(proj_w[j]);
    } else if (idx < 73728) {
        int j = idx - 36864;
        int k = j / 384, n = j - k * 384;
        g_WtFC1h[n * 96 + k] = __float2bfloat16(fc1_w[j]);
    } else if (idx < 110592) {
        int j = idx - 73728;
        int k = j / 96, n = j - k * 96;
        g_WtFC2h[n * 384 + k] = __float2bfloat16(fc2_w[j]);
    }
}

// ---------------------------------------------------------------------------
// cp.async bf16 mma GEMM: C[128,96] = A[128,K] @ Wt[96,K]^T
// MODE 0: qkv (q-scale)  MODE 1: proj (scatter+residual + fused LN2->bf16)
// MODE 2: fc1 (GELU->bf16)  MODE 3: fc2 (+residual -> d_out)
// ---------------------------------------------------------------------------
#define KPAD2 104                       // b16 units; 208B row stride, LDSM-clean
#define A_STG (128 * KPAD2 * 2)         // 26624 B
#define B_STG (96 * KPAD2 * 2)          // 19968 B
#define STAGE_BYTES (A_STG + B_STG)     // 46592 B
#define GEMM_SMEM_1 49664               // single-stage modes (epilogue dominates)
#define GEMM_SMEM_2 (2 * STAGE_BYTES)   // fc2: 93184 B

template <int MODE>
__global__ void __launch_bounds__(256) gemm_mma(const float* __restrict__ bias,
                                                const float* __restrict__ res,
                                                float* __restrict__ outp,
                                                int Kb,
                                                const float* __restrict__ g2,
                                                const float* __restrict__ b2)
{
    extern __shared__ __align__(16) char smraw[];
    float* Sf = (float*)smraw;   // epilogue staging [128][97]

    const __nv_bfloat16* A  = (MODE == 0) ? g_Hb : (MODE == 1) ? g_Ob
                            : (MODE == 2) ? g_X2b : g_FFb;
    const __nv_bfloat16* Wt = (MODE == 0) ? g_WtQKVh : (MODE == 1) ? g_WtPROJh
                            : (MODE == 2) ? g_WtFC1h : g_WtFC2h;

    int tid  = threadIdx.x;
    int wid  = tid >> 5, lane = tid & 31;
    int wr   = wid >> 1, wc = wid & 1;
    int g    = lane >> 2, c = lane & 3;
    int m0   = blockIdx.y * BM;
    int n0   = blockIdx.x * BN;

    uint32_t smem_base = (uint32_t)__cvta_generic_to_shared(smraw);

    const __nv_bfloat16* Agm = A  + (size_t)m0 * Kb;
    const __nv_bfloat16* Bgm = Wt + (size_t)n0 * Kb;

    auto stage = [&](int chunk, int buf) {
        uint32_t dstA = smem_base + buf * STAGE_BYTES;
        uint32_t dstB = dstA + A_STG;
        const __nv_bfloat16* As = Agm + chunk * 96;
        const __nv_bfloat16* Bs = Bgm + chunk * 96;
#pragma unroll
        for (int i = 0; i < 6; i++) {
            int idx = tid + (i << 8);
            int row = idx / 12, c16 = idx - row * 12;
            cp16(dstA + (uint32_t)((row * KPAD2 + c16 * 8) * 2),
                 As + (size_t)row * Kb + c16 * 8);
        }
#pragma unroll
        for (int i = 0; i < 5; i++) {
            int idx = tid + (i << 8);
            if (idx < 1152) {
                int row = idx / 12, c16 = idx - row * 12;
                cp16(dstB + (uint32_t)((row * KPAD2 + c16 * 8) * 2),
                     Bs + (size_t)row * Kb + c16 * 8);
            }
        }
        asm volatile("cp.async.commit_group;" ::: "memory");
    };

    int nc = Kb / 96;
    stage(0, 0);
    if (nc > 1) stage(1, 1);
    if (nc > 1) asm volatile("cp.async.wait_group 1;" ::: "memory");
    else        asm volatile("cp.async.wait_group 0;" ::: "memory");
    __syncthreads();

    float acc[2][6][4];
#pragma unroll
    for (int t = 0; t < 2; t++)
#pragma unroll
        for (int u = 0; u < 6; u++)
#pragma unroll
            for (int j = 0; j < 4; j++) acc[t][u][j] = 0.0f;

    int rowoff = lane & 15;
    int koff   = (lane >> 4) << 3;
    uint32_t aAddr0 = smem_base + (uint32_t)(((wr * 32 + rowoff) * KPAD2 + koff) * 2);
    uint32_t bAddr0 = smem_base + A_STG + (uint32_t)(((wc * 48 + rowoff) * KPAD2 + koff) * 2);

    for (int chv = 0; chv < nc; chv++) {
        uint32_t aBuf = aAddr0 + (chv & 1) * STAGE_BYTES;
        uint32_t bBuf = bAddr0 + (chv & 1) * STAGE_BYTES;
#pragma unroll
        for (int ks = 0; ks < 6; ks++) {
            uint32_t a[2][4];
#pragma unroll
            for (int t = 0; t < 2; t++)
                ldsm4(a[t][0], a[t][1], a[t][2], a[t][3],
                      aBuf + (uint32_t)((t * 16 * KPAD2 + ks * 16) * 2));
            uint32_t bq[6][2];
#pragma unroll
            for (int p = 0; p < 3; p++) {
                uint32_t q0, q1, q2, q3;
                ldsm4(q0, q1, q2, q3,
                      bBuf + (uint32_t)((p * 16 * KPAD2 + ks * 16) * 2));
                bq[2 * p][0] = q0; bq[2 * p + 1][0] = q1;
                bq[2 * p][1] = q2; bq[2 * p + 1][1] = q3;
            }
#pragma unroll
            for (int u = 0; u < 6; u++) {
                mma16(acc[0][u], a[0], bq[u][0], bq[u][1]);
                mma16(acc[1][u], a[1], bq[u][0], bq[u][1]);
            }
        }
        if (chv + 1 < nc) {
            __syncthreads();
            if (chv + 2 < nc) stage(chv + 2, chv & 1);
            if (chv + 2 < nc) asm volatile("cp.async.wait_group 1;" ::: "memory");
            else              asm volatile("cp.async.wait_group 0;" ::: "memory");
            __syncthreads();
        }
    }
    __syncthreads();

#pragma unroll
    for (int t = 0; t < 2; t++) {
#pragma unroll
        for (int u = 0; u < 6; u++) {
            int r0 = wr * 32 + t * 16 + g;
            int nn = wc * 48 + u * 8 + 2 * c;
            float b0 = __ldg(bias + n0 + nn);
            float b1 = __ldg(bias + n0 + nn + 1);
            float v0 = acc[t][u][0] + b0, v1 = acc[t][u][1] + b1;
            float v2 = acc[t][u][2] + b0, v3 = acc[t][u][3] + b1;
            if (MODE == 0 && n0 == 0) {
                v0 *= 0.17677669529663689f; v1 *= 0.17677669529663689f;
                v2 *= 0.17677669529663689f; v3 *= 0.17677669529663689f;
            }
            if (MODE == 2) {
                v0 = 0.5f * v0 * (1.0f + erff(v0 * 0.70710678118654752f));
                v1 = 0.5f * v1 * (1.0f + erff(v1 * 0.70710678118654752f));
                v2 = 0.5f * v2 * (1.0f + erff(v2 * 0.70710678118654752f));
                v3 = 0.5f * v3 * (1.0f + erff(v3 * 0.70710678118654752f));
            }
            Sf[r0 * 97 + nn] = v0;       Sf[r0 * 97 + nn + 1] = v1;
            Sf[(r0 + 8) * 97 + nn] = v2; Sf[(r0 + 8) * 97 + nn + 1] = v3;
        }
    }
    __syncthreads();

#pragma unroll
    for (int i = 0; i < 12; i++) {
        int idx = tid + (i << 8);
        int row = idx / 24, q4 = idx - row * 24;
        int m = m0 + row, n = n0 + (q4 << 2);
        float* sp = Sf + row * 97 + (q4 << 2);
        float4 v; v.x = sp[0]; v.y = sp[1]; v.z = sp[2]; v.w = sp[3];
        if (MODE == 0) {
            *(float4*)(g_QKV + (size_t)m * 288 + n) = v;
        } else if (MODE == 1) {
            int d0 = g_DST[m];
            float4 r = *(const float4*)(res + (size_t)d0 * 96 + n);
            v.x += r.x; v.y += r.y; v.z += r.z; v.w += r.w;
            *(float4*)(g_X + (size_t)d0 * 96 + n) = v;
            sp[0] = v.x; sp[1] = v.y; sp[2] = v.z; sp[3] = v.w;
        } else if (MODE == 2) {
            uint2 u;
            u.x = bf2(v.x, v.y); u.y = bf2(v.z, v.w);
            *(uint2*)(g_FFb + (size_t)m * 384 + n) = u;
        } else {
            float4 r = *(const float4*)(g_X + (size_t)m * 96 + n);
            v.x += r.x; v.y += r.y; v.z += r.z; v.w += r.w;
            *(float4*)(outp + (size_t)m * 96 + n) = v;
        }
    }

    if (MODE == 1) {
        __syncthreads();
        int row = tid >> 1, half = tid & 1;
        const float* rp = Sf + row * 97 + half * 48;
        float s = 0.f, ss = 0.f;
#pragma unroll
        for (int j = 0; j < 48; j++) {
            float v = rp[j];
            s += v; ss = fmaf(v, v, ss);
        }
        s  += __shfl_xor_sync(0xffffffffu, s, 1);
        ss += __shfl_xor_sync(0xffffffffu, ss, 1);
        float mean = s * (1.0f / 96.0f);
        float var  = ss * (1.0f / 96.0f) - mean * mean;
        float inv  = rsqrtf(var + 1e-5f);
        int d0 = g_DST[m0 + row];
        __nv_bfloat16* op = g_X2b + (size_t)d0 * 96 + half * 48;
#pragma unroll
        for (int j4 = 0; j4 < 12; j4++) {
            int n = half * 48 + j4 * 4;
            float o0 = (rp[j4 * 4]     - mean) * inv * __ldg(g2 + n)     + __ldg(b2 + n);
            float o1 = (rp[j4 * 4 + 1] - mean) * inv * __ldg(g2 + n + 1) + __ldg(b2 + n + 1);
            float o2 = (rp[j4 * 4 + 2] - mean) * inv * __ldg(g2 + n + 2) + __ldg(b2 + n + 2);
            float o3 = (rp[j4 * 4 + 3] - mean) * inv * __ldg(g2 + n + 3) + __ldg(b2 + n + 3);
            uint2 u; u.x = bf2(o0, o1); u.y = bf2(o2, o3);
            *(uint2*)(op + j4 * 4) = u;
        }
    }
}

// ---------------------------------------------------------------------------
// bf16 MMA attention: block = (window, head), 352 threads = 11 warps,
// warp owns 32 query rows. Flash over key chunks of 32, m16n8k16.
// K fragments: ldmatrix.x4; V fragments: ldmatrix.x4.trans;
// P->A fragment is pure bf16x2 packing (k16 pairs == C-fragment n pairs).
// ---------------------------------------------------------------------------
#define NPAD 352
#define KP 40                                // b16 units; 80B row, LDSM-clean
#define ATTN_SMEM (2 * NPAD * KP * 2)        // 56320 B

__global__ void __launch_bounds__(352, 1) attn_mma(const float* __restrict__ rpb)
{
    extern __shared__ __align__(16) char smraw[];
    __nv_bfloat16* Ksp = (__nv_bfloat16*)smraw;
    __nv_bfloat16* Vsp = Ksp + NPAD * KP;

    int w   = blockIdx.x / 3;
    int h   = blockIdx.x - w * 3;
    int tid = threadIdx.x;
    const float* base = g_QKV + (size_t)w * NTOK * 288;

    // stage K,V as bf16 pairs
    for (int i = tid; i < NTOK * 16; i += 352) {
        int n = i >> 4, j = (i & 15) << 1;
        const float* bp = base + n * 288 + h * 32 + j;
        float2 kv = *(const float2*)(bp + 96);
        float2 vv = *(const float2*)(bp + 192);
        *(uint32_t*)(Ksp + n * KP + j) = bf2(kv.x, kv.y);
        *(uint32_t*)(Vsp + n * KP + j) = bf2(vv.x, vv.y);
    }
    for (int i = NTOK * 16 + tid; i < NPAD * 16; i += 352) {
        int n = i >> 4, j = (i & 15) << 1;
        *(uint32_t*)(Ksp + n * KP + j) = 0;
        *(uint32_t*)(Vsp + n * KP + j) = 0;
    }
    __syncthreads();

    int wid  = tid >> 5, lane = tid & 31;
    int g    = lane >> 2, c = lane & 3;
    int q0   = wid * 32;

    int iH = w >> 5, iW = (w >> 2) & 7, iD = w & 3;
    int cls = ((iH == 7) << 2) | ((iW == 7) << 1) | (iD == 3);
    const float* SB = g_SB + (size_t)(cls * 3 + h) * NTOK * SBROW;

    uint32_t smem_base = (uint32_t)__cvta_generic_to_shared(smraw);
    uint32_t Kbase = smem_base;
    uint32_t Vbase = smem_base + NPAD * KP * 2;

    // ldmatrix lane address components (computed once)
    int l7  = lane & 7;
    int b3  = (lane >> 3) & 1;
    int b4  = (lane >> 4) & 1;
    // K (non-trans): key = kc + p*16 + b4*8 + l7 ; dim = ks*16 + b3*8
    uint32_t kAddr = Kbase + (uint32_t)((((b4 << 3) + l7) * KP + (b3 << 3)) * 2);
    // V (trans): key = kc + ks*16 + b3*8 + l7 ; dim = db*16 + b4*8
    uint32_t vAddr = Vbase + (uint32_t)((((b3 << 3) + l7) * KP + (b4 << 3)) * 2);

    // Q fragments (bf16, m16n8k16 A layout), direct from gmem, row-clamped
    uint32_t qa[2][2][4];
    const float* sbp[4];
#pragma unroll
    for (int t = 0; t < 2; t++) {
#pragma unroll
        for (int rr = 0; rr < 2; rr++) {
            int row = q0 + t * 16 + rr * 8 + g;
            int rc  = (row < NTOK) ? row : NTOK - 1;
            sbp[t * 2 + rr] = SB + (size_t)rc * SBROW;
            const float* qp = base + rc * 288 + h * 32;
#pragma unroll
            for (int ks = 0; ks < 2; ks++) {
                float2 p0 = *(const float2*)(qp + ks * 16 + 2 * c);
                float2 p1 = *(const float2*)(qp + ks * 16 + 2 * c + 8);
                qa[t][ks][rr]     = bf2(p0.x, p0.y);
                qa[t][ks][rr + 2] = bf2(p1.x, p1.y);
            }
        }
    }

    float mrun[4] = {-1e30f, -1e30f, -1e30f, -1e30f};
    float lrun[4] = {0.f, 0.f, 0.f, 0.f};
    float o[2][4][4];
#pragma unroll
    for (int t = 0; t < 2; t++)
#pragma unroll
        for (int nb = 0; nb < 4; nb++)
#pragma unroll
            for (int j = 0; j < 4; j++) o[t][nb][j] = 0.f;

    for (int kc = 0; kc < NPAD; kc += 32) {
        float sa[2][4][4];
#pragma unroll
        for (int t = 0; t < 2; t++)
#pragma unroll
            for (int nb = 0; nb < 4; nb++)
#pragma unroll
                for (int j = 0; j < 4; j++) sa[t][nb][j] = 0.f;

        // S = Q K^T : keys in pairs of n8 tiles, dims in two k16 steps
#pragma unroll
        for (int p = 0; p < 2; p++) {
#pragma unroll
            for (int ks = 0; ks < 2; ks++) {
                uint32_t k0, k1, k2, k3;
                ldsm4(k0, k1, k2, k3,
                      kAddr + (uint32_t)(((kc + p * 16) * KP + ks * 16) * 2));
                mma16(sa[0][2 * p],     qa[0][ks], k0, k1);
                mma16(sa[1][2 * p],     qa[1][ks], k0, k1);
                mma16(sa[0][2 * p + 1], qa[0][ks], k2, k3);
                mma16(sa[1][2 * p + 1], qa[1][ks], k2, k3);
            }
        }

        // bias + mask + padding from table
#pragma unroll
        for (int t = 0; t < 2; t++) {
#pragma unroll
            for (int nb = 0; nb < 4; nb++) {
                int coff = kc + nb * 8 + 2 * c;
                float2 bv0 = *(const float2*)(sbp[t * 2]     + coff);
                float2 bv1 = *(const float2*)(sbp[t * 2 + 1] + coff);
                sa[t][nb][0] += bv0.x; sa[t][nb][1] += bv0.y;
                sa[t][nb][2] += bv1.x; sa[t][nb][3] += bv1.y;
            }
        }

        // online softmax per row
#pragma unroll
        for (int ri = 0; ri < 4; ri++) {
            int t = ri >> 1, rr = ri & 1;
            float mx = -3e4f;
#pragma unroll
            for (int nb = 0; nb < 4; nb++)
                mx = fmaxf(mx, fmaxf(sa[t][nb][rr * 2], sa[t][nb][rr * 2 + 1]));
            mx = fmaxf(mx, __shfl_xor_sync(0xffffffffu, mx, 1));
            mx = fmaxf(mx, __shfl_xor_sync(0xffffffffu, mx, 2));
            float mnew = fmaxf(mrun[ri], mx);
            float corr = __expf(mrun[ri] - mnew);
            mrun[ri] = mnew;
            float ls = 0.f;
#pragma unroll
            for (int nb = 0; nb < 4; nb++) {
                float p0 = __expf(sa[t][nb][rr * 2]     - mnew);
                float p1 = __expf(sa[t][nb][rr * 2 + 1] - mnew);
                sa[t][nb][rr * 2]     = p0;
                sa[t][nb][rr * 2 + 1] = p1;
                ls += p0 + p1;
            }
            ls += __shfl_xor_sync(0xffffffffu, ls, 1);
            ls += __shfl_xor_sync(0xffffffffu, ls, 2);
            lrun[ri] = lrun[ri] * corr + ls;
#pragma unroll
            for (int nb = 0; nb < 4; nb++) {
                o[t][nb][rr * 2]     *= corr;
                o[t][nb][rr * 2 + 1] *= corr;
            }
        }

        // O += P V : P packs directly into A fragments (no shuffles)
#pragma unroll
        for (int ks = 0; ks < 2; ks++) {
            uint32_t pa[2][4];
#pragma unroll
            for (int t = 0; t < 2; t++) {
                pa[t][0] = bf2(sa[t][2 * ks][0],     sa[t][2 * ks][1]);
                pa[t][1] = bf2(sa[t][2 * ks][2],     sa[t][2 * ks][3]);
                pa[t][2] = bf2(sa[t][2 * ks + 1][0], sa[t][2 * ks + 1][1]);
                pa[t][3] = bf2(sa[t][2 * ks + 1][2], sa[t][2 * ks + 1][3]);
            }
#pragma unroll
            for (int db = 0; db < 2; db++) {
                uint32_t v0, v1, v2, v3;
                ldsm4t(v0, v1, v2, v3,
                       vAddr + (uint32_t)(((kc + ks * 16) * KP + db * 16) * 2));
                mma16(o[0][2 * db],     pa[0], v0, v1);
                mma16(o[1][2 * db],     pa[1], v0, v1);
                mma16(o[0][2 * db + 1], pa[0], v2, v3);
                mma16(o[1][2 * db + 1], pa[1], v2, v3);
            }
        }
    }

    float inv[4];
#pragma unroll
    for (int ri = 0; ri < 4; ri++) inv[ri] = 1.0f / lrun[ri];

#pragma unroll
    for (int t = 0; t < 2; t++) {
        int r0 = q0 + t * 16 + g;
#pragma unroll
        for (int rr = 0; rr < 2; rr++) {
            int row = r0 + rr * 8;
            if (row < NTOK) {
                int ri = t * 2 + rr;
                __nv_bfloat16* op = g_Ob + ((size_t)w * NTOK + row) * CDIM + h * 32;
#pragma unroll
                for (int nb = 0; nb < 4; nb++) {
                    uint32_t p = bf2(o[t][nb][rr * 2] * inv[ri],
                                     o[t][nb][rr * 2 + 1] * inv[ri]);
                    *(uint32_t*)(op + nb * 8 + 2 * c) = p;
                }
            }
        }
    }
}

// ---------------------------------------------------------------------------
// Launch
// ---------------------------------------------------------------------------
extern "C" void kernel_launch(void* const* d_in, const int* in_sizes, int n_in,
                              void* d_out, int out_size)
{
    const float* x      = (const float*)d_in[0];
    const float* n1g    = (const float*)d_in[1];
    const float* n1b    = (const float*)d_in[2];
    const float* qkv_w  = (const float*)d_in[3];
    const float* qkv_b  = (const float*)d_in[4];
    const float* rpb    = (const float*)d_in[5];
    const float* proj_w = (const float*)d_in[6];
    const float* proj_b = (const float*)d_in[7];
    const float* n2g    = (const float*)d_in[8];
    const float* n2b    = (const float*)d_in[9];
    const float* fc1_w  = (const float*)d_in[10];
    const float* fc1_b  = (const float*)d_in[11];
    const float* fc2_w  = (const float*)d_in[12];
    const float* fc2_b  = (const float*)d_in[13];
    float* out = (float*)d_out;

    cudaFuncSetAttribute(gemm_mma<0>, cudaFuncAttributeMaxDynamicSharedMemorySize, GEMM_SMEM_1);
    cudaFuncSetAttribute(gemm_mma<1>, cudaFuncAttributeMaxDynamicSharedMemorySize, GEMM_SMEM_1);
    cudaFuncSetAttribute(gemm_mma<2>, cudaFuncAttributeMaxDynamicSharedMemorySize, GEMM_SMEM_1);
    cudaFuncSetAttribute(gemm_mma<3>, cudaFuncAttributeMaxDynamicSharedMemorySize, GEMM_SMEM_2);
    cudaFuncSetAttribute(attn_mma, cudaFuncAttributeMaxDynamicSharedMemorySize, ATTN_SMEM);

    transpose_all<<<432, 256>>>(qkv_w, proj_w, fc1_w, fc2_w);
    bias_precompute<<<(24 * NTOK * SBROW + 255) / 256, 256>>>(rpb);

    ln_kernel<<<LTOK / 8, 256>>>(x, n1g, n1b);

    gemm_mma<0><<<dim3(3, 686), 256, GEMM_SMEM_1>>>(qkv_b, nullptr, nullptr, 96, nullptr, nullptr);

    attn_mma<<<NWIN * NHEAD, 352, ATTN_SMEM>>>(rpb);

    gemm_mma<1><<<dim3(1, 686), 256, GEMM_SMEM_1>>>(proj_b, x, nullptr, 96, n2g, n2b);

    gemm_mma<2><<<dim3(4, 686), 256, GEMM_SMEM_1>>>(fc1_b, nullptr, nullptr, 96, nullptr, nullptr);

    gemm_mma<3><<<dim3(1, 686), 256, GEMM_SMEM_2>>>(fc2_b, nullptr, out, 384, nullptr, nullptr);
}

// round 11
// speedup vs baseline: 1.5654x; 1.1726x over previous
#include <cuda_runtime.h>
#include <cuda_bf16.h>
#include <cstdint>

// ---------------------------------------------------------------------------
// Problem constants
// ---------------------------------------------------------------------------
#define HH   56
#define WWID 56
#define DDEP 28
#define LTOK 87808          // 56*56*28
#define CDIM 96
#define NWIN 256
#define NTOK 343
#define NHEAD 3
#define FF   384
#define BN   96             // GEMM N tile
#define BM   128            // GEMM M tile

// ---------------------------------------------------------------------------
// Scratch (device globals; no allocation allowed)
// ---------------------------------------------------------------------------
__device__ __align__(16) float g_X  [(size_t)LTOK * CDIM];
__device__ int g_DST[LTOK];
// bf16 activations
__device__ __align__(16) __nv_bfloat16 g_QKVh[(size_t)LTOK * 288];
__device__ __align__(16) __nv_bfloat16 g_Hb [(size_t)LTOK * CDIM];
__device__ __align__(16) __nv_bfloat16 g_Ob [(size_t)LTOK * CDIM];
__device__ __align__(16) __nv_bfloat16 g_X2b[(size_t)LTOK * CDIM];
__device__ __align__(16) __nv_bfloat16 g_FFb[(size_t)LTOK * FF];
// bf16 pre-transposed weights [N,K]
__device__ __align__(16) __nv_bfloat16 g_WtQKVh [288 * 96];
__device__ __align__(16) __nv_bfloat16 g_WtPROJh[96 * 96];
__device__ __align__(16) __nv_bfloat16 g_WtFC1h [384 * 96];
__device__ __align__(16) __nv_bfloat16 g_WtFC2h [96 * 384];
// precomputed bias+mask table: [8 classes][3 heads][343 rows][352 cols]
#define SBROW 352
__device__ __align__(16) float g_SB[24 * NTOK * SBROW];

// ---------------------------------------------------------------------------
// helpers
// ---------------------------------------------------------------------------
__device__ __forceinline__ void mma16(float* c, const uint32_t* a, uint32_t b0, uint32_t b1) {
    asm("mma.sync.aligned.m16n8k16.row.col.f32.bf16.bf16.f32 "
        "{%0,%1,%2,%3}, {%4,%5,%6,%7}, {%8,%9}, {%0,%1,%2,%3};"
        : "+f"(c[0]), "+f"(c[1]), "+f"(c[2]), "+f"(c[3])
        : "r"(a[0]), "r"(a[1]), "r"(a[2]), "r"(a[3]), "r"(b0), "r"(b1));
}
__device__ __forceinline__ void ldsm4(uint32_t& r0, uint32_t& r1, uint32_t& r2, uint32_t& r3,
                                      uint32_t addr) {
    asm volatile("ldmatrix.sync.aligned.m8n8.x4.shared.b16 {%0,%1,%2,%3}, [%4];"
        : "=r"(r0), "=r"(r1), "=r"(r2), "=r"(r3) : "r"(addr));
}
__device__ __forceinline__ void ldsm4t(uint32_t& r0, uint32_t& r1, uint32_t& r2, uint32_t& r3,
                                       uint32_t addr) {
    asm volatile("ldmatrix.sync.aligned.m8n8.x4.trans.shared.b16 {%0,%1,%2,%3}, [%4];"
        : "=r"(r0), "=r"(r1), "=r"(r2), "=r"(r3) : "r"(addr));
}
__device__ __forceinline__ uint32_t bf2(float lo, float hi) {
    uint32_t d;
    asm("cvt.rn.bf16x2.f32 %0, %1, %2;" : "=r"(d) : "f"(hi), "f"(lo));
    return d;
}
__device__ __forceinline__ void cp16(uint32_t dst, const void* src) {
    asm volatile("cp.async.cg.shared.global [%0], [%1], 16;" :: "r"(dst), "l"(src));
}

// ---------------------------------------------------------------------------
// Bias+mask table precompute: SB[cls][h][n][m]
// ---------------------------------------------------------------------------
__global__ void bias_precompute(const float* __restrict__ rpb)
{
    int gid = blockIdx.x * 256 + threadIdx.x;
    if (gid >= 24 * NTOK * SBROW) return;
    int m  = gid % SBROW;
    int t  = gid / SBROW;
    int n  = t % NTOK;
    int ch = t / NTOK;
    int h  = ch % 3, cls = ch / 3;
    float v;
    if (m >= NTOK) {
        v = -30000.0f;
    } else {
        int an = n / 49, rn = n - an * 49, bn = rn / 7, cn = rn - bn * 7;
        int am = m / 49, rm = m - am * 49, bm = rm / 7, cm = rm - bm * 7;
        int sub_n = an * 169 + bn * 13 + cn;
        int sub_m = am * 169 + bm * 13 + cm;
        v = rpb[(1098 + sub_n - sub_m) * 3 + h];
        int bh = (cls >> 2) & 1, bw = (cls >> 1) & 1, bd = cls & 1;
        int rgn_n = ((bh ? (an < 4 ? 1 : 2) : 0) * 3 + (bw ? (bn < 4 ? 1 : 2) : 0)) * 3
                  + (bd ? (cn < 4 ? 1 : 2) : 0);
        int rgn_m = ((bh ? (am < 4 ? 1 : 2) : 0) * 3 + (bw ? (bm < 4 ? 1 : 2) : 0)) * 3
                  + (bd ? (cm < 4 ? 1 : 2) : 0);
        if (rgn_n != rgn_m) v -= 100.0f;
    }
    g_SB[gid] = v;
}

// ---------------------------------------------------------------------------
// LayerNorm #1 (one warp per token): gather + shift + partition -> bf16
// ---------------------------------------------------------------------------
__global__ void __launch_bounds__(256) ln_kernel(const float* __restrict__ in,
                                                 const float* __restrict__ gamma,
                                                 const float* __restrict__ beta)
{
    int gw   = (blockIdx.x * 256 + threadIdx.x) >> 5;
    int lane = threadIdx.x & 31;
    if (gw >= LTOK) return;

    int w = gw / NTOK, n = gw - w * NTOK;
    int iH = w >> 5, iW = (w >> 2) & 7, iD = w & 3;
    int a = n / 49; int r = n - a * 49; int b = r / 7; int c = r - b * 7;
    int th = iH * 7 + a + 3; if (th >= HH)   th -= HH;
    int tw = iW * 7 + b + 3; if (tw >= WWID) tw -= WWID;
    int td = iD * 7 + c + 3; if (td >= DDEP) td -= DDEP;
    int src = (th * WWID + tw) * DDEP + td;
    if (lane == 0) g_DST[gw] = src;
    const float* inp = in + (size_t)src * CDIM;
    __nv_bfloat16* outp = g_Hb + (size_t)gw * CDIM;

    float v0 = inp[lane], v1 = inp[lane + 32], v2 = inp[lane + 64];
    float s  = v0 + v1 + v2;
    float ss = fmaf(v0, v0, fmaf(v1, v1, v2 * v2));
#pragma unroll
    for (int o = 16; o; o >>= 1) {
        s  += __shfl_xor_sync(0xffffffffu, s, o);
        ss += __shfl_xor_sync(0xffffffffu, ss, o);
    }
    float mean = s * (1.0f / 96.0f);
    float var  = ss * (1.0f / 96.0f) - mean * mean;
    float inv  = rsqrtf(var + 1e-5f);
    outp[lane]      = __float2bfloat16((v0 - mean) * inv * gamma[lane]      + beta[lane]);
    outp[lane + 32] = __float2bfloat16((v1 - mean) * inv * gamma[lane + 32] + beta[lane + 32]);
    outp[lane + 64] = __float2bfloat16((v2 - mean) * inv * gamma[lane + 64] + beta[lane + 64]);
}

// ---------------------------------------------------------------------------
// All weight transposes in one launch: W[K,N] -> bf16 Wt[N,K]
// ---------------------------------------------------------------------------
__global__ void transpose_all(const float* __restrict__ qkv_w,
                              const float* __restrict__ proj_w,
                              const float* __restrict__ fc1_w,
                              const float* __restrict__ fc2_w)
{
    int idx = blockIdx.x * 256 + threadIdx.x;
    if (idx < 27648) {
        int k = idx / 288, n = idx - k * 288;
        g_WtQKVh[n * 96 + k] = __float2bfloat16(qkv_w[idx]);
    } else if (idx < 36864) {
        int j = idx - 27648;
        int k = j / 96, n = j - k * 96;
        g_WtPROJh[n * 96 + k] = __float2bfloat16(proj_w[j]);
    } else if (idx < 73728) {
        int j = idx - 36864;
        int k = j / 384, n = j - k * 384;
        g_WtFC1h[n * 96 + k] = __float2bfloat16(fc1_w[j]);
    } else if (idx < 110592) {
        int j = idx - 73728;
        int k = j / 96, n = j - k * 96;
        g_WtFC2h[n * 384 + k] = __float2bfloat16(fc2_w[j]);
    }
}

// ---------------------------------------------------------------------------
// cp.async bf16 mma GEMM: C[128,96] = A[128,K] @ Wt[96,K]^T
// MODE 0: qkv (q-scale, bf16 out)  MODE 1: proj (scatter+residual + fused LN2)
// MODE 2: fc1 (GELU->bf16)         MODE 3: fc2 (+residual -> d_out)
// ---------------------------------------------------------------------------
#define KPAD2 104                       // b16 units; 208B row stride, LDSM-clean
#define A_STG (128 * KPAD2 * 2)         // 26624 B
#define B_STG (96 * KPAD2 * 2)          // 19968 B
#define STAGE_BYTES (A_STG + B_STG)     // 46592 B
#define GEMM_SMEM_1 49664               // single-stage modes (epilogue dominates)
#define GEMM_SMEM_2 (2 * STAGE_BYTES)   // fc2: 93184 B

template <int MODE>
__global__ void __launch_bounds__(256, 3) gemm_mma(const float* __restrict__ bias,
                                                   const float* __restrict__ res,
                                                   float* __restrict__ outp,
                                                   int Kb,
                                                   const float* __restrict__ g2,
                                                   const float* __restrict__ b2)
{
    extern __shared__ __align__(16) char smraw[];
    float* Sf = (float*)smraw;   // epilogue staging [128][97]

    const __nv_bfloat16* A  = (MODE == 0) ? g_Hb : (MODE == 1) ? g_Ob
                            : (MODE == 2) ? g_X2b : g_FFb;
    const __nv_bfloat16* Wt = (MODE == 0) ? g_WtQKVh : (MODE == 1) ? g_WtPROJh
                            : (MODE == 2) ? g_WtFC1h : g_WtFC2h;

    int tid  = threadIdx.x;
    int wid  = tid >> 5, lane = tid & 31;
    int wr   = wid >> 1, wc = wid & 1;
    int g    = lane >> 2, c = lane & 3;
    int m0   = blockIdx.y * BM;
    int n0   = blockIdx.x * BN;

    uint32_t smem_base = (uint32_t)__cvta_generic_to_shared(smraw);

    const __nv_bfloat16* Agm = A  + (size_t)m0 * Kb;
    const __nv_bfloat16* Bgm = Wt + (size_t)n0 * Kb;

    auto stage = [&](int chunk, int buf) {
        uint32_t dstA = smem_base + buf * STAGE_BYTES;
        uint32_t dstB = dstA + A_STG;
        const __nv_bfloat16* As = Agm + chunk * 96;
        const __nv_bfloat16* Bs = Bgm + chunk * 96;
#pragma unroll
        for (int i = 0; i < 6; i++) {
            int idx = tid + (i << 8);
            int row = idx / 12, c16 = idx - row * 12;
            cp16(dstA + (uint32_t)((row * KPAD2 + c16 * 8) * 2),
                 As + (size_t)row * Kb + c16 * 8);
        }
#pragma unroll
        for (int i = 0; i < 5; i++) {
            int idx = tid + (i << 8);
            if (idx < 1152) {
                int row = idx / 12, c16 = idx - row * 12;
                cp16(dstB + (uint32_t)((row * KPAD2 + c16 * 8) * 2),
                     Bs + (size_t)row * Kb + c16 * 8);
            }
        }
        asm volatile("cp.async.commit_group;" ::: "memory");
    };

    int nc = Kb / 96;
    stage(0, 0);
    if (nc > 1) stage(1, 1);
    if (nc > 1) asm volatile("cp.async.wait_group 1;" ::: "memory");
    else        asm volatile("cp.async.wait_group 0;" ::: "memory");
    __syncthreads();

    float acc[2][6][4];
#pragma unroll
    for (int t = 0; t < 2; t++)
#pragma unroll
        for (int u = 0; u < 6; u++)
#pragma unroll
            for (int j = 0; j < 4; j++) acc[t][u][j] = 0.0f;

    int rowoff = lane & 15;
    int koff   = (lane >> 4) << 3;
    uint32_t aAddr0 = smem_base + (uint32_t)(((wr * 32 + rowoff) * KPAD2 + koff) * 2);
    uint32_t bAddr0 = smem_base + A_STG + (uint32_t)(((wc * 48 + rowoff) * KPAD2 + koff) * 2);

    for (int chv = 0; chv < nc; chv++) {
        uint32_t aBuf = aAddr0 + (chv & 1) * STAGE_BYTES;
        uint32_t bBuf = bAddr0 + (chv & 1) * STAGE_BYTES;
#pragma unroll
        for (int ks = 0; ks < 6; ks++) {
            uint32_t a[2][4];
#pragma unroll
            for (int t = 0; t < 2; t++)
                ldsm4(a[t][0], a[t][1], a[t][2], a[t][3],
                      aBuf + (uint32_t)((t * 16 * KPAD2 + ks * 16) * 2));
            uint32_t bq[6][2];
#pragma unroll
            for (int p = 0; p < 3; p++) {
                uint32_t q0, q1, q2, q3;
                ldsm4(q0, q1, q2, q3,
                      bBuf + (uint32_t)((p * 16 * KPAD2 + ks * 16) * 2));
                bq[2 * p][0] = q0; bq[2 * p + 1][0] = q1;
                bq[2 * p][1] = q2; bq[2 * p + 1][1] = q3;
            }
#pragma unroll
            for (int u = 0; u < 6; u++) {
                mma16(acc[0][u], a[0], bq[u][0], bq[u][1]);
                mma16(acc[1][u], a[1], bq[u][0], bq[u][1]);
            }
        }
        if (chv + 1 < nc) {
            __syncthreads();
            if (chv + 2 < nc) stage(chv + 2, chv & 1);
            if (chv + 2 < nc) asm volatile("cp.async.wait_group 1;" ::: "memory");
            else              asm volatile("cp.async.wait_group 0;" ::: "memory");
            __syncthreads();
        }
    }
    __syncthreads();

#pragma unroll
    for (int t = 0; t < 2; t++) {
#pragma unroll
        for (int u = 0; u < 6; u++) {
            int r0 = wr * 32 + t * 16 + g;
            int nn = wc * 48 + u * 8 + 2 * c;
            float b0 = __ldg(bias + n0 + nn);
            float b1 = __ldg(bias + n0 + nn + 1);
            float v0 = acc[t][u][0] + b0, v1 = acc[t][u][1] + b1;
            float v2 = acc[t][u][2] + b0, v3 = acc[t][u][3] + b1;
            if (MODE == 0 && n0 == 0) {
                v0 *= 0.17677669529663689f; v1 *= 0.17677669529663689f;
                v2 *= 0.17677669529663689f; v3 *= 0.17677669529663689f;
            }
            if (MODE == 2) {
                v0 = 0.5f * v0 * (1.0f + erff(v0 * 0.70710678118654752f));
                v1 = 0.5f * v1 * (1.0f + erff(v1 * 0.70710678118654752f));
                v2 = 0.5f * v2 * (1.0f + erff(v2 * 0.70710678118654752f));
                v3 = 0.5f * v3 * (1.0f + erff(v3 * 0.70710678118654752f));
            }
            Sf[r0 * 97 + nn] = v0;       Sf[r0 * 97 + nn + 1] = v1;
            Sf[(r0 + 8) * 97 + nn] = v2; Sf[(r0 + 8) * 97 + nn + 1] = v3;
        }
    }
    __syncthreads();

#pragma unroll
    for (int i = 0; i < 12; i++) {
        int idx = tid + (i << 8);
        int row = idx / 24, q4 = idx - row * 24;
        int m = m0 + row, n = n0 + (q4 << 2);
        float* sp = Sf + row * 97 + (q4 << 2);
        float4 v; v.x = sp[0]; v.y = sp[1]; v.z = sp[2]; v.w = sp[3];
        if (MODE == 0) {
            uint2 u;
            u.x = bf2(v.x, v.y); u.y = bf2(v.z, v.w);
            *(uint2*)(g_QKVh + (size_t)m * 288 + n) = u;
        } else if (MODE == 1) {
            int d0 = g_DST[m];
            float4 r = *(const float4*)(res + (size_t)d0 * 96 + n);
            v.x += r.x; v.y += r.y; v.z += r.z; v.w += r.w;
            *(float4*)(g_X + (size_t)d0 * 96 + n) = v;
            sp[0] = v.x; sp[1] = v.y; sp[2] = v.z; sp[3] = v.w;
        } else if (MODE == 2) {
            uint2 u;
            u.x = bf2(v.x, v.y); u.y = bf2(v.z, v.w);
            *(uint2*)(g_FFb + (size_t)m * 384 + n) = u;
        } else {
            float4 r = *(const float4*)(g_X + (size_t)m * 96 + n);
            v.x += r.x; v.y += r.y; v.z += r.z; v.w += r.w;
            *(float4*)(outp + (size_t)m * 96 + n) = v;
        }
    }

    if (MODE == 1) {
        __syncthreads();
        int row = tid >> 1, half = tid & 1;
        const float* rp = Sf + row * 97 + half * 48;
        float s = 0.f, ss = 0.f;
#pragma unroll
        for (int j = 0; j < 48; j++) {
            float v = rp[j];
            s += v; ss = fmaf(v, v, ss);
        }
        s  += __shfl_xor_sync(0xffffffffu, s, 1);
        ss += __shfl_xor_sync(0xffffffffu, ss, 1);
        float mean = s * (1.0f / 96.0f);
        float var  = ss * (1.0f / 96.0f) - mean * mean;
        float inv  = rsqrtf(var + 1e-5f);
        int d0 = g_DST[m0 + row];
        __nv_bfloat16* op = g_X2b + (size_t)d0 * 96 + half * 48;
#pragma unroll
        for (int j4 = 0; j4 < 12; j4++) {
            int n = half * 48 + j4 * 4;
            float o0 = (rp[j4 * 4]     - mean) * inv * __ldg(g2 + n)     + __ldg(b2 + n);
            float o1 = (rp[j4 * 4 + 1] - mean) * inv * __ldg(g2 + n + 1) + __ldg(b2 + n + 1);
            float o2 = (rp[j4 * 4 + 2] - mean) * inv * __ldg(g2 + n + 2) + __ldg(b2 + n + 2);
            float o3 = (rp[j4 * 4 + 3] - mean) * inv * __ldg(g2 + n + 3) + __ldg(b2 + n + 3);
            uint2 u; u.x = bf2(o0, o1); u.y = bf2(o2, o3);
            *(uint2*)(op + j4 * 4) = u;
        }
    }
}

// ---------------------------------------------------------------------------
// bf16 MMA attention: block = (window, head), 352 threads = 11 warps,
// warp owns 32 query rows. Flash over key chunks of 32, m16n8k16.
// K/V staged via cp.async from bf16 g_QKVh; Q fragments direct uint32 loads.
// ---------------------------------------------------------------------------
#define NPAD 352
#define KP 40                                // b16 units; 80B row, LDSM-clean
#define ATTN_SMEM (2 * NPAD * KP * 2)        // 56320 B

__global__ void __launch_bounds__(352, 1) attn_mma(const float* __restrict__ rpb)
{
    extern __shared__ __align__(16) char smraw[];
    __nv_bfloat16* Ksp = (__nv_bfloat16*)smraw;
    __nv_bfloat16* Vsp = Ksp + NPAD * KP;

    int w   = blockIdx.x / 3;
    int h   = blockIdx.x - w * 3;
    int tid = threadIdx.x;
    const __nv_bfloat16* base = g_QKVh + (size_t)w * NTOK * 288;

    uint32_t smem_base = (uint32_t)__cvta_generic_to_shared(smraw);
    uint32_t Kbase = smem_base;
    uint32_t Vbase = smem_base + NPAD * KP * 2;

    // stage K,V via cp.async: 4 x 16B per row each
    for (int i = tid; i < NTOK * 4; i += 352) {
        int n = i >> 2, j = (i & 3) << 3;     // j in {0,8,16,24} bf16
        const __nv_bfloat16* bp = base + n * 288 + h * 32 + j;
        cp16(Kbase + (uint32_t)((n * KP + j) * 2), bp + 96);
        cp16(Vbase + (uint32_t)((n * KP + j) * 2), bp + 192);
    }
    // zero padding rows
    for (int i = NTOK * 16 + tid; i < NPAD * 16; i += 352) {
        int n = i >> 4, j = (i & 15) << 1;
        *(uint32_t*)(Ksp + n * KP + j) = 0;
        *(uint32_t*)(Vsp + n * KP + j) = 0;
    }
    asm volatile("cp.async.commit_group;" ::: "memory");
    asm volatile("cp.async.wait_group 0;" ::: "memory");
    __syncthreads();

    int wid  = tid >> 5, lane = tid & 31;
    int g    = lane >> 2, c = lane & 3;
    int q0   = wid * 32;

    int iH = w >> 5, iW = (w >> 2) & 7, iD = w & 3;
    int cls = ((iH == 7) << 2) | ((iW == 7) << 1) | (iD == 3);
    const float* SB = g_SB + (size_t)(cls * 3 + h) * NTOK * SBROW;

    // ldmatrix lane address components
    int l7  = lane & 7;
    int b3  = (lane >> 3) & 1;
    int b4  = (lane >> 4) & 1;
    uint32_t kAddr = Kbase + (uint32_t)((((b4 << 3) + l7) * KP + (b3 << 3)) * 2);
    uint32_t vAddr = Vbase + (uint32_t)((((b3 << 3) + l7) * KP + (b4 << 3)) * 2);

    // Q fragments (bf16 pairs straight from gmem), row-clamped
    uint32_t qa[2][2][4];
    const float* sbp[4];
#pragma unroll
    for (int t = 0; t < 2; t++) {
#pragma unroll
        for (int rr = 0; rr < 2; rr++) {
            int row = q0 + t * 16 + rr * 8 + g;
            int rc  = (row < NTOK) ? row : NTOK - 1;
            sbp[t * 2 + rr] = SB + (size_t)rc * SBROW;
            const __nv_bfloat16* qp = base + rc * 288 + h * 32;
#pragma unroll
            for (int ks = 0; ks < 2; ks++) {
                qa[t][ks][rr]     = *(const uint32_t*)(qp + ks * 16 + 2 * c);
                qa[t][ks][rr + 2] = *(const uint32_t*)(qp + ks * 16 + 2 * c + 8);
            }
        }
    }

    float mrun[4] = {-1e30f, -1e30f, -1e30f, -1e30f};
    float lrun[4] = {0.f, 0.f, 0.f, 0.f};
    float o[2][4][4];
#pragma unroll
    for (int t = 0; t < 2; t++)
#pragma unroll
        for (int nb = 0; nb < 4; nb++)
#pragma unroll
            for (int j = 0; j < 4; j++) o[t][nb][j] = 0.f;

    for (int kc = 0; kc < NPAD; kc += 32) {
        float sa[2][4][4];
#pragma unroll
        for (int t = 0; t < 2; t++)
#pragma unroll
            for (int nb = 0; nb < 4; nb++)
#pragma unroll
                for (int j = 0; j < 4; j++) sa[t][nb][j] = 0.f;

#pragma unroll
        for (int p = 0; p < 2; p++) {
#pragma unroll
            for (int ks = 0; ks < 2; ks++) {
                uint32_t k0, k1, k2, k3;
                ldsm4(k0, k1, k2, k3,
                      kAddr + (uint32_t)(((kc + p * 16) * KP + ks * 16) * 2));
                mma16(sa[0][2 * p],     qa[0][ks], k0, k1);
                mma16(sa[1][2 * p],     qa[1][ks], k0, k1);
                mma16(sa[0][2 * p + 1], qa[0][ks], k2, k3);
                mma16(sa[1][2 * p + 1], qa[1][ks], k2, k3);
            }
        }

#pragma unroll
        for (int t = 0; t < 2; t++) {
#pragma unroll
            for (int nb = 0; nb < 4; nb++) {
                int coff = kc + nb * 8 + 2 * c;
                float2 bv0 = *(const float2*)(sbp[t * 2]     + coff);
                float2 bv1 = *(const float2*)(sbp[t * 2 + 1] + coff);
                sa[t][nb][0] += bv0.x; sa[t][nb][1] += bv0.y;
                sa[t][nb][2] += bv1.x; sa[t][nb][3] += bv1.y;
            }
        }

#pragma unroll
        for (int ri = 0; ri < 4; ri++) {
            int t = ri >> 1, rr = ri & 1;
            float mx = -3e4f;
#pragma unroll
            for (int nb = 0; nb < 4; nb++)
                mx = fmaxf(mx, fmaxf(sa[t][nb][rr * 2], sa[t][nb][rr * 2 + 1]));
            mx = fmaxf(mx, __shfl_xor_sync(0xffffffffu, mx, 1));
            mx = fmaxf(mx, __shfl_xor_sync(0xffffffffu, mx, 2));
            float mnew = fmaxf(mrun[ri], mx);
            float corr = __expf(mrun[ri] - mnew);
            mrun[ri] = mnew;
            float ls = 0.f;
#pragma unroll
            for (int nb = 0; nb < 4; nb++) {
                float p0 = __expf(sa[t][nb][rr * 2]     - mnew);
                float p1 = __expf(sa[t][nb][rr * 2 + 1] - mnew);
                sa[t][nb][rr * 2]     = p0;
                sa[t][nb][rr * 2 + 1] = p1;
                ls += p0 + p1;
            }
            ls += __shfl_xor_sync(0xffffffffu, ls, 1);
            ls += __shfl_xor_sync(0xffffffffu, ls, 2);
            lrun[ri] = lrun[ri] * corr + ls;
#pragma unroll
            for (int nb = 0; nb < 4; nb++) {
                o[t][nb][rr * 2]     *= corr;
                o[t][nb][rr * 2 + 1] *= corr;
            }
        }

#pragma unroll
        for (int ks = 0; ks < 2; ks++) {
            uint32_t pa[2][4];
#pragma unroll
            for (int t = 0; t < 2; t++) {
                pa[t][0] = bf2(sa[t][2 * ks][0],     sa[t][2 * ks][1]);
                pa[t][1] = bf2(sa[t][2 * ks][2],     sa[t][2 * ks][3]);
                pa[t][2] = bf2(sa[t][2 * ks + 1][0], sa[t][2 * ks + 1][1]);
                pa[t][3] = bf2(sa[t][2 * ks + 1][2], sa[t][2 * ks + 1][3]);
            }
#pragma unroll
            for (int db = 0; db < 2; db++) {
                uint32_t v0, v1, v2, v3;
                ldsm4t(v0, v1, v2, v3,
                       vAddr + (uint32_t)(((kc + ks * 16) * KP + db * 16) * 2));
                mma16(o[0][2 * db],     pa[0], v0, v1);
                mma16(o[1][2 * db],     pa[1], v0, v1);
                mma16(o[0][2 * db + 1], pa[0], v2, v3);
                mma16(o[1][2 * db + 1], pa[1], v2, v3);
            }
        }
    }

    float inv[4];
#pragma unroll
    for (int ri = 0; ri < 4; ri++) inv[ri] = 1.0f / lrun[ri];

#pragma unroll
    for (int t = 0; t < 2; t++) {
        int r0 = q0 + t * 16 + g;
#pragma unroll
        for (int rr = 0; rr < 2; rr++) {
            int row = r0 + rr * 8;
            if (row < NTOK) {
                int ri = t * 2 + rr;
                __nv_bfloat16* op = g_Ob + ((size_t)w * NTOK + row) * CDIM + h * 32;
#pragma unroll
                for (int nb = 0; nb < 4; nb++) {
                    uint32_t p = bf2(o[t][nb][rr * 2] * inv[ri],
                                     o[t][nb][rr * 2 + 1] * inv[ri]);
                    *(uint32_t*)(op + nb * 8 + 2 * c) = p;
                }
            }
        }
    }
}

// ---------------------------------------------------------------------------
// Launch
// ---------------------------------------------------------------------------
extern "C" void kernel_launch(void* const* d_in, const int* in_sizes, int n_in,
                              void* d_out, int out_size)
{
    const float* x      = (const float*)d_in[0];
    const float* n1g    = (const float*)d_in[1];
    const float* n1b    = (const float*)d_in[2];
    const float* qkv_w  = (const float*)d_in[3];
    const float* qkv_b  = (const float*)d_in[4];
    const float* rpb    = (const float*)d_in[5];
    const float* proj_w = (const float*)d_in[6];
    const float* proj_b = (const float*)d_in[7];
    const float* n2g    = (const float*)d_in[8];
    const float* n2b    = (const float*)d_in[9];
    const float* fc1_w  = (const float*)d_in[10];
    const float* fc1_b  = (const float*)d_in[11];
    const float* fc2_w  = (const float*)d_in[12];
    const float* fc2_b  = (const float*)d_in[13];
    float* out = (float*)d_out;

    cudaFuncSetAttribute(gemm_mma<0>, cudaFuncAttributeMaxDynamicSharedMemorySize, GEMM_SMEM_1);
    cudaFuncSetAttribute(gemm_mma<1>, cudaFuncAttributeMaxDynamicSharedMemorySize, GEMM_SMEM_1);
    cudaFuncSetAttribute(gemm_mma<2>, cudaFuncAttributeMaxDynamicSharedMemorySize, GEMM_SMEM_1);
    cudaFuncSetAttribute(gemm_mma<3>, cudaFuncAttributeMaxDynamicSharedMemorySize, GEMM_SMEM_2);
    cudaFuncSetAttribute(attn_mma, cudaFuncAttributeMaxDynamicSharedMemorySize, ATTN_SMEM);

    transpose_all<<<432, 256>>>(qkv_w, proj_w, fc1_w, fc2_w);
    bias_precompute<<<(24 * NTOK * SBROW + 255) / 256, 256>>>(rpb);

    ln_kernel<<<LTOK / 8, 256>>>(x, n1g, n1b);

    gemm_mma<0><<<dim3(3, 686), 256, GEMM_SMEM_1>>>(qkv_b, nullptr, nullptr, 96, nullptr, nullptr);

    attn_mma<<<NWIN * NHEAD, 352, ATTN_SMEM>>>(rpb);

    gemm_mma<1><<<dim3(1, 686), 256, GEMM_SMEM_1>>>(proj_b, x, nullptr, 96, n2g, n2b);

    gemm_mma<2><<<dim3(4, 686), 256, GEMM_SMEM_1>>>(fc1_b, nullptr, nullptr, 96, nullptr, nullptr);

    gemm_mma<3><<<dim3(1, 686), 256, GEMM_SMEM_2>>>(fc2_b, nullptr, out, 384, nullptr, nullptr);
}